// round 1
// baseline (speedup 1.0000x reference)
#include <cuda_runtime.h>

// ---------------------------------------------------------------------------
// Problem constants
// ---------------------------------------------------------------------------
#define BATCH   8
#define CH      256          // channels in = channels out (DIM)
#define HW      16384        // 128*128
#define IMG     (CH * HW)    // per-batch elements = 4194304
#define GROUPS  32
#define GSZ     (CH / GROUPS)   // 8 channels per group
#define PSZ     8               // patch size
#define NPIX    64              // pixels per window
#define EPS     1e-5f

// Scratch: raw (pre-GroupNorm) projections + per-(tensor,b,group) stats.
static __device__ float g_qraw[(size_t)BATCH * IMG];
static __device__ float g_kraw[(size_t)BATCH * IMG];
static __device__ float g_mean[2 * BATCH * GROUPS];
static __device__ float g_rstd[2 * BATCH * GROUPS];

// ---------------------------------------------------------------------------
// Kernel 1: projection GEMM.  Y[b,o,p] = sum_c W[o,c] * X[b,c,p]
// Tile 128x128x16, 256 threads, 8x8 per-thread microtile.
// grid = (1024, 2, 2): x = pixel tile (over b*HW), y = output-channel tile,
// z selects (wq,x_low)->g_qraw vs (wk,x_high)->g_kraw.
// ---------------------------------------------------------------------------
__global__ void __launch_bounds__(256, 2) proj_gemm(
    const float* __restrict__ wq, const float* __restrict__ wk,
    const float* __restrict__ xlo, const float* __restrict__ xhi)
{
    __shared__ float As[16][132];   // [k][m], padded
    __shared__ float Bs[16][128];   // [k][n]

    const int tid = threadIdx.x;
    const float* Wm = blockIdx.z ? wk : wq;
    const float* X  = blockIdx.z ? xhi : xlo;
    float*       Y  = blockIdx.z ? g_kraw : g_qraw;

    const int bb = blockIdx.x >> 7;            // batch (128 pixel-tiles/batch)
    const int p0 = (blockIdx.x & 127) << 7;    // pixel offset within batch
    const int m0 = blockIdx.y << 7;            // output channel offset

    const float* Xb = X + (size_t)bb * IMG + p0;

    const int ty = tid >> 4;   // 0..15
    const int tx = tid & 15;   // 0..15

    float acc[8][8];
#pragma unroll
    for (int i = 0; i < 8; i++)
#pragma unroll
        for (int j = 0; j < 8; j++) acc[i][j] = 0.f;

    for (int kt = 0; kt < CH; kt += 16) {
        // Load A tile (128 rows x 16 k), transpose into As[k][m]
#pragma unroll
        for (int i = 0; i < 2; i++) {
            int idx = i * 256 + tid;           // 0..511
            int row = idx >> 2;                // 0..127
            int c4  = idx & 3;                 // 0..3
            float4 v = *(const float4*)(Wm + (size_t)(m0 + row) * CH + kt + c4 * 4);
            As[c4 * 4 + 0][row] = v.x;
            As[c4 * 4 + 1][row] = v.y;
            As[c4 * 4 + 2][row] = v.z;
            As[c4 * 4 + 3][row] = v.w;
        }
        // Load B tile (16 k x 128 pixels), coalesced rows
#pragma unroll
        for (int i = 0; i < 2; i++) {
            int idx = i * 256 + tid;           // 0..511
            int row = idx >> 5;                // 0..15
            int c4  = idx & 31;                // 0..31
            *(float4*)&Bs[row][c4 * 4] =
                *(const float4*)(Xb + (size_t)(kt + row) * HW + c4 * 4);
        }
        __syncthreads();

#pragma unroll
        for (int k = 0; k < 16; k++) {
            float a[8], bv[8];
            *(float4*)&a[0]  = *(float4*)&As[k][ty * 8];
            *(float4*)&a[4]  = *(float4*)&As[k][ty * 8 + 4];
            *(float4*)&bv[0] = *(float4*)&Bs[k][tx * 8];
            *(float4*)&bv[4] = *(float4*)&Bs[k][tx * 8 + 4];
#pragma unroll
            for (int i = 0; i < 8; i++)
#pragma unroll
                for (int j = 0; j < 8; j++)
                    acc[i][j] = fmaf(a[i], bv[j], acc[i][j]);
        }
        __syncthreads();
    }

    // Epilogue: store raw projection
    float* Yb = Y + (size_t)bb * IMG + p0 + tx * 8;
#pragma unroll
    for (int r = 0; r < 8; r++) {
        size_t ro = (size_t)(m0 + ty * 8 + r) * HW;
        float4 v0 = make_float4(acc[r][0], acc[r][1], acc[r][2], acc[r][3]);
        float4 v1 = make_float4(acc[r][4], acc[r][5], acc[r][6], acc[r][7]);
        *(float4*)(Yb + ro)     = v0;
        *(float4*)(Yb + ro + 4) = v1;
    }
}

// ---------------------------------------------------------------------------
// Kernel 2: GroupNorm statistics.
// One block per (tensor, batch, group): reduces a contiguous 131072-float
// segment (8 channels x 16384 pixels). Deterministic tree reduction.
// ---------------------------------------------------------------------------
__global__ void __launch_bounds__(256) stats_kernel()
{
    const int id  = blockIdx.x;        // 0..511
    const int t   = id >> 8;           // tensor: 0=q, 1=k
    const int b   = (id >> 5) & 7;
    const int g   = id & 31;
    const int tid = threadIdx.x;

    const float* src = (t ? g_kraw : g_qraw) + (size_t)b * IMG + (size_t)g * (GSZ * HW);
    const float4* p4 = (const float4*)src;

    float s = 0.f, sq = 0.f;
#pragma unroll 4
    for (int i = 0; i < 128; i++) {
        float4 v = p4[(size_t)i * 256 + tid];
        s  += v.x + v.y + v.z + v.w;
        sq += v.x * v.x + v.y * v.y + v.z * v.z + v.w * v.w;
    }

    __shared__ float rs[256], rq[256];
    rs[tid] = s; rq[tid] = sq;
    __syncthreads();
    for (int o = 128; o > 0; o >>= 1) {
        if (tid < o) { rs[tid] += rs[tid + o]; rq[tid] += rq[tid + o]; }
        __syncthreads();
    }
    if (tid == 0) {
        const float invN = 1.f / (float)(GSZ * HW);
        float m   = rs[0] * invN;
        float var = rq[0] * invN - m * m;
        g_mean[id] = m;
        g_rstd[id] = rsqrtf(var + EPS);
    }
}

// ---------------------------------------------------------------------------
// Kernel 3: windowed attention + residual. One CTA per 8x8 window.
// smem: sK[256][68], sQ[256][68] (reused as Kt[64][260]), sP[64][68] (reused
// as output staging [64c][64pix]).
// ---------------------------------------------------------------------------
#define KS_STRIDE 68
#define KT_STRIDE 260
#define SQ_OFF    (CH * KS_STRIDE)          // 17408
#define SP_OFF    (2 * CH * KS_STRIDE)      // 34816
#define AT_SMEM_FLOATS (SP_OFF + NPIX * KS_STRIDE)   // 39168
#define AT_SMEM_BYTES  (AT_SMEM_FLOATS * 4)          // 156672

__global__ void __launch_bounds__(256) attn_kernel(
    const float* __restrict__ xlo, float* __restrict__ outp,
    const float* __restrict__ gq, const float* __restrict__ bq,
    const float* __restrict__ gk, const float* __restrict__ bk)
{
    extern __shared__ float sm[];
    float* sK = sm;            // [CH][KS_STRIDE]  : k_norm, channel-major
    float* sQ = sm + SQ_OFF;   // [CH][KS_STRIDE]  : q_norm, later Kt[64][260]
    float* sP = sm + SP_OFF;   // [64][KS_STRIDE]  : attn probs, later out stage

    const int tid = threadIdx.x;
    const int bb  = blockIdx.x >> 8;
    const int rem = blockIdx.x & 255;
    const int wh  = rem >> 4;
    const int ww  = rem & 15;
    const int base_px = (wh << 3) * 128 + (ww << 3);   // y0*128 + x0

    const float* qb = g_qraw + (size_t)bb * IMG;
    const float* kb = g_kraw + (size_t)bb * IMG;

    // -------- Phase A: load + GroupNorm-normalize q,k into smem --------
#pragma unroll
    for (int s = 0; s < 8; s++) {
        int seg = s * 256 + tid;      // 0..2047
        int c   = seg >> 3;           // channel
        int p1  = seg & 7;            // patch row
        size_t ga = (size_t)c * HW + base_px + p1 * 128;
        int g = c >> 3;
        int pix = p1 * 8;

        // q
        {
            float m = g_mean[bb * 32 + g], r = g_rstd[bb * 32 + g];
            float a = r * gq[c];
            float d = bq[c] - m * a;
            float4 v0 = *(const float4*)(qb + ga);
            float4 v1 = *(const float4*)(qb + ga + 4);
            float4 o0 = make_float4(fmaf(v0.x,a,d), fmaf(v0.y,a,d), fmaf(v0.z,a,d), fmaf(v0.w,a,d));
            float4 o1 = make_float4(fmaf(v1.x,a,d), fmaf(v1.y,a,d), fmaf(v1.z,a,d), fmaf(v1.w,a,d));
            *(float4*)&sQ[c * KS_STRIDE + pix]     = o0;
            *(float4*)&sQ[c * KS_STRIDE + pix + 4] = o1;
        }
        // k
        {
            float m = g_mean[256 + bb * 32 + g], r = g_rstd[256 + bb * 32 + g];
            float a = r * gk[c];
            float d = bk[c] - m * a;
            float4 v0 = *(const float4*)(kb + ga);
            float4 v1 = *(const float4*)(kb + ga + 4);
            float4 o0 = make_float4(fmaf(v0.x,a,d), fmaf(v0.y,a,d), fmaf(v0.z,a,d), fmaf(v0.w,a,d));
            float4 o1 = make_float4(fmaf(v1.x,a,d), fmaf(v1.y,a,d), fmaf(v1.z,a,d), fmaf(v1.w,a,d));
            *(float4*)&sK[c * KS_STRIDE + pix]     = o0;
            *(float4*)&sK[c * KS_STRIDE + pix + 4] = o1;
        }
    }
    __syncthreads();

    // -------- Phase B: S = q^T k (64x64), 4x4 per thread, then softmax ----
    const int ty = tid >> 4, tx = tid & 15;
    const int i0 = ty * 4, j0 = tx * 4;

    float S[4][4];
#pragma unroll
    for (int i = 0; i < 4; i++)
#pragma unroll
        for (int j = 0; j < 4; j++) S[i][j] = 0.f;

#pragma unroll 8
    for (int c = 0; c < CH; c++) {
        float4 a  = *(float4*)&sQ[c * KS_STRIDE + i0];
        float4 bv = *(float4*)&sK[c * KS_STRIDE + j0];
        const float av[4] = {a.x, a.y, a.z, a.w};
        const float bw[4] = {bv.x, bv.y, bv.z, bv.w};
#pragma unroll
        for (int i = 0; i < 4; i++)
#pragma unroll
            for (int j = 0; j < 4; j++)
                S[i][j] = fmaf(av[i], bw[j], S[i][j]);
    }

    // scale by 1/sqrt(256) = 1/16, row softmax (row spans 16 lanes in tx)
#pragma unroll
    for (int r = 0; r < 4; r++) {
#pragma unroll
        for (int j = 0; j < 4; j++) S[r][j] *= 0.0625f;
        float mx = fmaxf(fmaxf(S[r][0], S[r][1]), fmaxf(S[r][2], S[r][3]));
#pragma unroll
        for (int off = 8; off >= 1; off >>= 1)
            mx = fmaxf(mx, __shfl_xor_sync(0xffffffffu, mx, off));
        float sum = 0.f;
#pragma unroll
        for (int j = 0; j < 4; j++) { S[r][j] = __expf(S[r][j] - mx); sum += S[r][j]; }
#pragma unroll
        for (int off = 8; off >= 1; off >>= 1)
            sum += __shfl_xor_sync(0xffffffffu, sum, off);
        float inv = 1.f / sum;
#pragma unroll
        for (int j = 0; j < 4; j++) S[r][j] *= inv;
    }
    __syncthreads();   // all S-reads of sQ done; sQ region can be reused

    // -------- Phase C: write P to smem, transpose sK -> Kt (in sQ region) --
#pragma unroll
    for (int r = 0; r < 4; r++)
#pragma unroll
        for (int j = 0; j < 4; j++)
            sP[(i0 + r) * KS_STRIDE + j0 + j] = S[r][j];

    float* Kt = sQ;    // [64][KT_STRIDE]: Kt[j][c] = k_norm at pixel j, chan c
#pragma unroll 4
    for (int t = 0; t < 64; t++) {
        int idx = t * 256 + tid;       // 0..16383
        int c = idx >> 6;
        int j = idx & 63;
        Kt[j * KT_STRIDE + c] = sK[c * KS_STRIDE + j];
    }
    __syncthreads();

    // -------- Phase D: out[i][c] = sum_j P[i][j] * Kt[j][c], 4x16/thread ---
    const int c0 = tx * 16;
    float o[4][16];
#pragma unroll
    for (int i = 0; i < 4; i++)
#pragma unroll
        for (int j = 0; j < 16; j++) o[i][j] = 0.f;

#pragma unroll 4
    for (int j = 0; j < 64; j++) {
        float a0 = sP[(i0 + 0) * KS_STRIDE + j];
        float a1 = sP[(i0 + 1) * KS_STRIDE + j];
        float a2 = sP[(i0 + 2) * KS_STRIDE + j];
        float a3 = sP[(i0 + 3) * KS_STRIDE + j];
        float bv[16];
        *(float4*)&bv[0]  = *(float4*)&Kt[j * KT_STRIDE + c0];
        *(float4*)&bv[4]  = *(float4*)&Kt[j * KT_STRIDE + c0 + 4];
        *(float4*)&bv[8]  = *(float4*)&Kt[j * KT_STRIDE + c0 + 8];
        *(float4*)&bv[12] = *(float4*)&Kt[j * KT_STRIDE + c0 + 12];
#pragma unroll
        for (int cc = 0; cc < 16; cc++) {
            o[0][cc] = fmaf(a0, bv[cc], o[0][cc]);
            o[1][cc] = fmaf(a1, bv[cc], o[1][cc]);
            o[2][cc] = fmaf(a2, bv[cc], o[2][cc]);
            o[3][cc] = fmaf(a3, bv[cc], o[3][cc]);
        }
    }

    // -------- Phase E: stage + write output (+ residual x_low), 4 chunks ---
    float* sO = sP;   // reuse: [64 c_local][KS_STRIDE pixels]
    for (int ch = 0; ch < 4; ch++) {
        __syncthreads();
        if ((tx >> 2) == ch) {
            int cl0 = (tx & 3) * 16;
#pragma unroll
            for (int r = 0; r < 4; r++)
#pragma unroll
                for (int cc = 0; cc < 16; cc++)
                    sO[(cl0 + cc) * KS_STRIDE + i0 + r] = o[r][cc];
        }
        __syncthreads();
#pragma unroll
        for (int s = 0; s < 2; s++) {
            int seg = s * 256 + tid;   // 0..511
            int cl  = seg >> 3;        // 0..63
            int p1  = seg & 7;
            int c   = ch * 64 + cl;
            size_t ga = (size_t)bb * IMG + (size_t)c * HW + base_px + p1 * 128;
            float4 v0 = *(float4*)&sO[cl * KS_STRIDE + p1 * 8];
            float4 v1 = *(float4*)&sO[cl * KS_STRIDE + p1 * 8 + 4];
            float4 x0 = *(const float4*)(xlo + ga);
            float4 x1 = *(const float4*)(xlo + ga + 4);
            v0.x += x0.x; v0.y += x0.y; v0.z += x0.z; v0.w += x0.w;
            v1.x += x1.x; v1.y += x1.y; v1.z += x1.z; v1.w += x1.w;
            *(float4*)(outp + ga)     = v0;
            *(float4*)(outp + ga + 4) = v1;
        }
    }
}

// ---------------------------------------------------------------------------
// Launcher
// ---------------------------------------------------------------------------
extern "C" void kernel_launch(void* const* d_in, const int* in_sizes, int n_in,
                              void* d_out, int out_size)
{
    const float* x_low  = (const float*)d_in[0];
    const float* x_high = (const float*)d_in[1];
    const float* wq     = (const float*)d_in[2];
    const float* wk     = (const float*)d_in[3];
    const float* gq     = (const float*)d_in[4];
    const float* bq     = (const float*)d_in[5];
    const float* gk     = (const float*)d_in[6];
    const float* bk     = (const float*)d_in[7];
    float* outp = (float*)d_out;

    // 1) raw projections (both tensors in one launch via grid.z)
    proj_gemm<<<dim3(1024, 2, 2), 256>>>(wq, wk, x_low, x_high);

    // 2) GroupNorm statistics
    stats_kernel<<<512, 256>>>();

    // 3) normalize + windowed attention + residual
    cudaFuncSetAttribute(attn_kernel,
                         cudaFuncAttributeMaxDynamicSharedMemorySize,
                         AT_SMEM_BYTES);
    attn_kernel<<<2048, 256, AT_SMEM_BYTES>>>(x_low, outp, gq, bq, gk, bk);
}

// round 3
// speedup vs baseline: 1.4285x; 1.4285x over previous
#include <cuda_runtime.h>
#include <cstdint>

// ---------------------------------------------------------------------------
// Problem constants
// ---------------------------------------------------------------------------
#define BATCH   8
#define CH      256
#define HW      16384
#define IMG     (CH * HW)
#define GROUPS  32
#define GSZ     (CH / GROUPS)
#define NPIX    64
#define EPS     1e-5f

static __device__ float g_qraw[(size_t)BATCH * IMG];
static __device__ float g_kraw[(size_t)BATCH * IMG];
static __device__ float g_mean[2 * BATCH * GROUPS];
static __device__ float g_rstd[2 * BATCH * GROUPS];

// ---------------------------------------------------------------------------
// tf32 helpers (legacy mma.sync path — works on plain sm_103 PTX target)
// ---------------------------------------------------------------------------
__device__ __forceinline__ uint32_t f2tf32(float f) {
    uint32_t r;
    asm("cvt.rna.tf32.f32 %0, %1;" : "=r"(r) : "f"(f));
    return r;
}

__device__ __forceinline__ void mma1688(float d[4], const uint32_t a[4],
                                        uint32_t b0, uint32_t b1) {
    asm volatile(
        "mma.sync.aligned.m16n8k8.row.col.f32.tf32.tf32.f32 "
        "{%0,%1,%2,%3}, {%4,%5,%6,%7}, {%8,%9}, {%0,%1,%2,%3};"
        : "+f"(d[0]), "+f"(d[1]), "+f"(d[2]), "+f"(d[3])
        : "r"(a[0]), "r"(a[1]), "r"(a[2]), "r"(a[3]), "r"(b0), "r"(b1));
}

// ---------------------------------------------------------------------------
// Kernel 1: projection GEMM via legacy tensor-core mma (tf32).
// D[m,n] = sum_k W[m,k] * X[k,n].  CTA tile 128m x 128n, K chunks of 32.
// A staged in fragment order (LDS.128 conflict-free hot loads);
// B staged row-layout [k][132].
// grid = (2 m-tiles, 1024 pixel-tiles, 2 tensors).
// ---------------------------------------------------------------------------
#define BS_STRIDE 132

__global__ void __launch_bounds__(256, 2) proj_mma(
    const float* __restrict__ wq, const float* __restrict__ wk,
    const float* __restrict__ xlo, const float* __restrict__ xhi)
{
    // A fragment buffer: [mb(8)][ks(4)][lane(32)][reg(4)] = 4096 floats
    __shared__ uint32_t Af[4096];
    __shared__ uint32_t Bs[32 * BS_STRIDE];

    const int tid  = threadIdx.x;
    const int wid  = tid >> 5;
    const int lane = tid & 31;

    const float* W = blockIdx.z ? wk : wq;
    const float* X = blockIdx.z ? xhi : xlo;
    float*       Y = blockIdx.z ? g_kraw : g_qraw;

    const int bb = blockIdx.y >> 7;
    const int p0 = (blockIdx.y & 127) << 7;
    const int m0 = blockIdx.x << 7;

    const float* Wb = W + (size_t)m0 * CH;
    const float* Xb = X + (size_t)bb * IMG + p0;

    const int wm = wid >> 2;          // warp m index (0..1) -> 64 rows
    const int wn = wid & 3;           // warp n index (0..3) -> 32 cols

    float acc[4][4][4];
#pragma unroll
    for (int i = 0; i < 4; i++)
#pragma unroll
        for (int j = 0; j < 4; j++)
#pragma unroll
            for (int r = 0; r < 4; r++) acc[i][j][r] = 0.f;

#pragma unroll 1
    for (int c = 0; c < 8; c++) {
        const int kc = c << 5;
        __syncthreads();   // previous chunk fully consumed

        // ---- stage A in fragment order ----
#pragma unroll
        for (int i = 0; i < 4; i++) {
            int idx = i * 256 + tid;
            int m  = idx >> 3;          // 0..127
            int kq = idx & 7;           // float4 index within 32-k chunk
            float4 w = *(const float4*)(Wb + (size_t)m * CH + kc + kq * 4);
            float wv[4] = {w.x, w.y, w.z, w.w};
            int mb = m >> 4;
            int rbit = (m >> 3) & 1;
            int lanebase = (m & 7) << 2;
#pragma unroll
            for (int e = 0; e < 4; e++) {
                int k = kq * 4 + e;
                int ks = k >> 3;
                int reg = rbit | (((k >> 2) & 1) << 1);
                Af[((mb * 4 + ks) << 7) + ((lanebase + (k & 3)) << 2) + reg] =
                    f2tf32(wv[e]);
            }
        }
        // ---- stage B row-layout [k][n] ----
#pragma unroll
        for (int i = 0; i < 4; i++) {
            int idx = i * 256 + tid;
            int k  = idx >> 5;
            int nq = idx & 31;
            float4 v = *(const float4*)(Xb + (size_t)(kc + k) * HW + nq * 4);
            uint4 t;
            t.x = f2tf32(v.x); t.y = f2tf32(v.y);
            t.z = f2tf32(v.z); t.w = f2tf32(v.w);
            *(uint4*)&Bs[k * BS_STRIDE + nq * 4] = t;
        }
        __syncthreads();

        // ---- compute: 4 k-steps of 8 ----
#pragma unroll
        for (int ks = 0; ks < 4; ks++) {
            uint32_t afr[4][4];
#pragma unroll
            for (int mb = 0; mb < 4; mb++) {
                int mbg = wm * 4 + mb;
                *(uint4*)afr[mb] =
                    *(uint4*)&Af[((mbg * 4 + ks) << 7) + (lane << 2)];
            }
            uint32_t bfr[4][2];
            const int krow = ks * 8 + (lane & 3);
            const int ncol = wn * 32 + (lane >> 2);
#pragma unroll
            for (int nb = 0; nb < 4; nb++) {
                bfr[nb][0] = Bs[krow * BS_STRIDE + ncol + nb * 8];
                bfr[nb][1] = Bs[(krow + 4) * BS_STRIDE + ncol + nb * 8];
            }
#pragma unroll
            for (int mb = 0; mb < 4; mb++)
#pragma unroll
                for (int nb = 0; nb < 4; nb++)
                    mma1688(acc[mb][nb], afr[mb], bfr[nb][0], bfr[nb][1]);
        }
    }

    // ---- epilogue: write fp32 raw projection ----
    float* Yb = Y + (size_t)bb * IMG + p0;
    const int rl = lane >> 2;            // 0..7
    const int cl = (lane & 3) * 2;       // 0,2,4,6
#pragma unroll
    for (int mb = 0; mb < 4; mb++) {
        int mrow = m0 + wm * 64 + mb * 16 + rl;
#pragma unroll
        for (int nb = 0; nb < 4; nb++) {
            int ncol = wn * 32 + nb * 8 + cl;
            float2 v0 = make_float2(acc[mb][nb][0], acc[mb][nb][1]);
            float2 v1 = make_float2(acc[mb][nb][2], acc[mb][nb][3]);
            *(float2*)(Yb + (size_t)mrow * HW + ncol)       = v0;
            *(float2*)(Yb + (size_t)(mrow + 8) * HW + ncol) = v1;
        }
    }
}

// ---------------------------------------------------------------------------
// Kernel 2: GroupNorm statistics (unchanged).
// ---------------------------------------------------------------------------
__global__ void __launch_bounds__(256) stats_kernel()
{
    const int id  = blockIdx.x;
    const int t   = id >> 8;
    const int b   = (id >> 5) & 7;
    const int g   = id & 31;
    const int tid = threadIdx.x;

    const float* src = (t ? g_kraw : g_qraw) + (size_t)b * IMG + (size_t)g * (GSZ * HW);
    const float4* p4 = (const float4*)src;

    float s = 0.f, sq = 0.f;
#pragma unroll 4
    for (int i = 0; i < 128; i++) {
        float4 v = p4[(size_t)i * 256 + tid];
        s  += v.x + v.y + v.z + v.w;
        sq += v.x * v.x + v.y * v.y + v.z * v.z + v.w * v.w;
    }

    __shared__ float rs[256], rq[256];
    rs[tid] = s; rq[tid] = sq;
    __syncthreads();
    for (int o = 128; o > 0; o >>= 1) {
        if (tid < o) { rs[tid] += rs[tid + o]; rq[tid] += rq[tid + o]; }
        __syncthreads();
    }
    if (tid == 0) {
        const float invN = 1.f / (float)(GSZ * HW);
        float m   = rs[0] * invN;
        float var = rq[0] * invN - m * m;
        g_mean[id] = m;
        g_rstd[id] = rsqrtf(var + EPS);
    }
}

// ---------------------------------------------------------------------------
// Kernel 3: windowed attention + residual (unchanged, known-good).
// ---------------------------------------------------------------------------
#define KS_STRIDE 68
#define KT_STRIDE 260
#define SQ_OFF    (CH * KS_STRIDE)
#define SP_OFF    (2 * CH * KS_STRIDE)
#define AT_SMEM_FLOATS (SP_OFF + NPIX * KS_STRIDE)
#define AT_SMEM_BYTES  (AT_SMEM_FLOATS * 4)

__global__ void __launch_bounds__(256) attn_kernel(
    const float* __restrict__ xlo, float* __restrict__ outp,
    const float* __restrict__ gq, const float* __restrict__ bq,
    const float* __restrict__ gk, const float* __restrict__ bk)
{
    extern __shared__ float smf[];
    float* sK = smf;
    float* sQ = smf + SQ_OFF;
    float* sP = smf + SP_OFF;

    const int tid = threadIdx.x;
    const int bb  = blockIdx.x >> 8;
    const int rem = blockIdx.x & 255;
    const int wh  = rem >> 4;
    const int ww  = rem & 15;
    const int base_px = (wh << 3) * 128 + (ww << 3);

    const float* qb = g_qraw + (size_t)bb * IMG;
    const float* kb = g_kraw + (size_t)bb * IMG;

#pragma unroll
    for (int s = 0; s < 8; s++) {
        int seg = s * 256 + tid;
        int c   = seg >> 3;
        int p1  = seg & 7;
        size_t ga = (size_t)c * HW + base_px + p1 * 128;
        int g = c >> 3;
        int pix = p1 * 8;
        {
            float m = g_mean[bb * 32 + g], r = g_rstd[bb * 32 + g];
            float a = r * gq[c];
            float d = bq[c] - m * a;
            float4 v0 = *(const float4*)(qb + ga);
            float4 v1 = *(const float4*)(qb + ga + 4);
            float4 o0 = make_float4(fmaf(v0.x,a,d), fmaf(v0.y,a,d), fmaf(v0.z,a,d), fmaf(v0.w,a,d));
            float4 o1 = make_float4(fmaf(v1.x,a,d), fmaf(v1.y,a,d), fmaf(v1.z,a,d), fmaf(v1.w,a,d));
            *(float4*)&sQ[c * KS_STRIDE + pix]     = o0;
            *(float4*)&sQ[c * KS_STRIDE + pix + 4] = o1;
        }
        {
            float m = g_mean[256 + bb * 32 + g], r = g_rstd[256 + bb * 32 + g];
            float a = r * gk[c];
            float d = bk[c] - m * a;
            float4 v0 = *(const float4*)(kb + ga);
            float4 v1 = *(const float4*)(kb + ga + 4);
            float4 o0 = make_float4(fmaf(v0.x,a,d), fmaf(v0.y,a,d), fmaf(v0.z,a,d), fmaf(v0.w,a,d));
            float4 o1 = make_float4(fmaf(v1.x,a,d), fmaf(v1.y,a,d), fmaf(v1.z,a,d), fmaf(v1.w,a,d));
            *(float4*)&sK[c * KS_STRIDE + pix]     = o0;
            *(float4*)&sK[c * KS_STRIDE + pix + 4] = o1;
        }
    }
    __syncthreads();

    const int ty = tid >> 4, tx = tid & 15;
    const int i0 = ty * 4, j0 = tx * 4;

    float S[4][4];
#pragma unroll
    for (int i = 0; i < 4; i++)
#pragma unroll
        for (int j = 0; j < 4; j++) S[i][j] = 0.f;

#pragma unroll 8
    for (int c = 0; c < CH; c++) {
        float4 a  = *(float4*)&sQ[c * KS_STRIDE + i0];
        float4 bv = *(float4*)&sK[c * KS_STRIDE + j0];
        const float av[4] = {a.x, a.y, a.z, a.w};
        const float bw[4] = {bv.x, bv.y, bv.z, bv.w};
#pragma unroll
        for (int i = 0; i < 4; i++)
#pragma unroll
            for (int j = 0; j < 4; j++)
                S[i][j] = fmaf(av[i], bw[j], S[i][j]);
    }

#pragma unroll
    for (int r = 0; r < 4; r++) {
#pragma unroll
        for (int j = 0; j < 4; j++) S[r][j] *= 0.0625f;
        float mx = fmaxf(fmaxf(S[r][0], S[r][1]), fmaxf(S[r][2], S[r][3]));
#pragma unroll
        for (int off = 8; off >= 1; off >>= 1)
            mx = fmaxf(mx, __shfl_xor_sync(0xffffffffu, mx, off));
        float sum = 0.f;
#pragma unroll
        for (int j = 0; j < 4; j++) { S[r][j] = __expf(S[r][j] - mx); sum += S[r][j]; }
#pragma unroll
        for (int off = 8; off >= 1; off >>= 1)
            sum += __shfl_xor_sync(0xffffffffu, sum, off);
        float inv = 1.f / sum;
#pragma unroll
        for (int j = 0; j < 4; j++) S[r][j] *= inv;
    }
    __syncthreads();

#pragma unroll
    for (int r = 0; r < 4; r++)
#pragma unroll
        for (int j = 0; j < 4; j++)
            sP[(i0 + r) * KS_STRIDE + j0 + j] = S[r][j];

    float* Kt = sQ;
#pragma unroll 4
    for (int t = 0; t < 64; t++) {
        int idx = t * 256 + tid;
        int c = idx >> 6;
        int j = idx & 63;
        Kt[j * KT_STRIDE + c] = sK[c * KS_STRIDE + j];
    }
    __syncthreads();

    const int c0 = tx * 16;
    float o[4][16];
#pragma unroll
    for (int i = 0; i < 4; i++)
#pragma unroll
        for (int j = 0; j < 16; j++) o[i][j] = 0.f;

#pragma unroll 4
    for (int j = 0; j < 64; j++) {
        float a0 = sP[(i0 + 0) * KS_STRIDE + j];
        float a1 = sP[(i0 + 1) * KS_STRIDE + j];
        float a2 = sP[(i0 + 2) * KS_STRIDE + j];
        float a3 = sP[(i0 + 3) * KS_STRIDE + j];
        float bv[16];
        *(float4*)&bv[0]  = *(float4*)&Kt[j * KT_STRIDE + c0];
        *(float4*)&bv[4]  = *(float4*)&Kt[j * KT_STRIDE + c0 + 4];
        *(float4*)&bv[8]  = *(float4*)&Kt[j * KT_STRIDE + c0 + 8];
        *(float4*)&bv[12] = *(float4*)&Kt[j * KT_STRIDE + c0 + 12];
#pragma unroll
        for (int cc = 0; cc < 16; cc++) {
            o[0][cc] = fmaf(a0, bv[cc], o[0][cc]);
            o[1][cc] = fmaf(a1, bv[cc], o[1][cc]);
            o[2][cc] = fmaf(a2, bv[cc], o[2][cc]);
            o[3][cc] = fmaf(a3, bv[cc], o[3][cc]);
        }
    }

    float* sO = sP;
    for (int ch = 0; ch < 4; ch++) {
        __syncthreads();
        if ((tx >> 2) == ch) {
            int cl0 = (tx & 3) * 16;
#pragma unroll
            for (int r = 0; r < 4; r++)
#pragma unroll
                for (int cc = 0; cc < 16; cc++)
                    sO[(cl0 + cc) * KS_STRIDE + i0 + r] = o[r][cc];
        }
        __syncthreads();
#pragma unroll
        for (int s = 0; s < 2; s++) {
            int seg = s * 256 + tid;
            int cl  = seg >> 3;
            int p1  = seg & 7;
            int c   = ch * 64 + cl;
            size_t ga = (size_t)bb * IMG + (size_t)c * HW + base_px + p1 * 128;
            float4 v0 = *(float4*)&sO[cl * KS_STRIDE + p1 * 8];
            float4 v1 = *(float4*)&sO[cl * KS_STRIDE + p1 * 8 + 4];
            float4 x0 = *(const float4*)(xlo + ga);
            float4 x1 = *(const float4*)(xlo + ga + 4);
            v0.x += x0.x; v0.y += x0.y; v0.z += x0.z; v0.w += x0.w;
            v1.x += x1.x; v1.y += x1.y; v1.z += x1.z; v1.w += x1.w;
            *(float4*)(outp + ga)     = v0;
            *(float4*)(outp + ga + 4) = v1;
        }
    }
}

// ---------------------------------------------------------------------------
// Launcher
// ---------------------------------------------------------------------------
extern "C" void kernel_launch(void* const* d_in, const int* in_sizes, int n_in,
                              void* d_out, int out_size)
{
    const float* x_low  = (const float*)d_in[0];
    const float* x_high = (const float*)d_in[1];
    const float* wq     = (const float*)d_in[2];
    const float* wk     = (const float*)d_in[3];
    const float* gq     = (const float*)d_in[4];
    const float* bq     = (const float*)d_in[5];
    const float* gk     = (const float*)d_in[6];
    const float* bk     = (const float*)d_in[7];
    float* outp = (float*)d_out;

    proj_mma<<<dim3(2, 1024, 2), 256>>>(wq, wk, x_low, x_high);

    stats_kernel<<<512, 256>>>();

    cudaFuncSetAttribute(attn_kernel,
                         cudaFuncAttributeMaxDynamicSharedMemorySize,
                         AT_SMEM_BYTES);
    attn_kernel<<<2048, 256, AT_SMEM_BYTES>>>(x_low, outp, gq, bq, gk, bk);
}

// round 4
// speedup vs baseline: 2.0856x; 1.4600x over previous
#include <cuda_runtime.h>
#include <cstdint>

// ---------------------------------------------------------------------------
// Problem constants
// ---------------------------------------------------------------------------
#define BATCH   8
#define CH      256
#define HW      16384
#define IMG     (CH * HW)
#define GROUPS  32
#define GSZ     (CH / GROUPS)
#define NPIX    64
#define EPS     1e-5f

static __device__ float g_qraw[(size_t)BATCH * IMG];
static __device__ float g_kraw[(size_t)BATCH * IMG];
static __device__ float g_mean[2 * BATCH * GROUPS];
static __device__ float g_rstd[2 * BATCH * GROUPS];

// ---------------------------------------------------------------------------
// tf32 helpers (legacy mma.sync path — works on plain sm_103 PTX target)
// ---------------------------------------------------------------------------
__device__ __forceinline__ uint32_t f2tf32(float f) {
    uint32_t r;
    asm("cvt.rna.tf32.f32 %0, %1;" : "=r"(r) : "f"(f));
    return r;
}

__device__ __forceinline__ void mma1688(float d[4], const uint32_t a[4],
                                        uint32_t b0, uint32_t b1) {
    asm volatile(
        "mma.sync.aligned.m16n8k8.row.col.f32.tf32.tf32.f32 "
        "{%0,%1,%2,%3}, {%4,%5,%6,%7}, {%8,%9}, {%0,%1,%2,%3};"
        : "+f"(d[0]), "+f"(d[1]), "+f"(d[2]), "+f"(d[3])
        : "r"(a[0]), "r"(a[1]), "r"(a[2]), "r"(a[3]), "r"(b0), "r"(b1));
}

// ---------------------------------------------------------------------------
// Kernel 1: projection GEMM via legacy tensor-core mma (tf32). (unchanged)
// ---------------------------------------------------------------------------
#define BS_STRIDE 132

__global__ void __launch_bounds__(256, 2) proj_mma(
    const float* __restrict__ wq, const float* __restrict__ wk,
    const float* __restrict__ xlo, const float* __restrict__ xhi)
{
    __shared__ uint32_t Af[4096];
    __shared__ uint32_t Bs[32 * BS_STRIDE];

    const int tid  = threadIdx.x;
    const int wid  = tid >> 5;
    const int lane = tid & 31;

    const float* W = blockIdx.z ? wk : wq;
    const float* X = blockIdx.z ? xhi : xlo;
    float*       Y = blockIdx.z ? g_kraw : g_qraw;

    const int bb = blockIdx.y >> 7;
    const int p0 = (blockIdx.y & 127) << 7;
    const int m0 = blockIdx.x << 7;

    const float* Wb = W + (size_t)m0 * CH;
    const float* Xb = X + (size_t)bb * IMG + p0;

    const int wm = wid >> 2;
    const int wn = wid & 3;

    float acc[4][4][4];
#pragma unroll
    for (int i = 0; i < 4; i++)
#pragma unroll
        for (int j = 0; j < 4; j++)
#pragma unroll
            for (int r = 0; r < 4; r++) acc[i][j][r] = 0.f;

#pragma unroll 1
    for (int c = 0; c < 8; c++) {
        const int kc = c << 5;
        __syncthreads();

#pragma unroll
        for (int i = 0; i < 4; i++) {
            int idx = i * 256 + tid;
            int m  = idx >> 3;
            int kq = idx & 7;
            float4 w = *(const float4*)(Wb + (size_t)m * CH + kc + kq * 4);
            float wv[4] = {w.x, w.y, w.z, w.w};
            int mb = m >> 4;
            int rbit = (m >> 3) & 1;
            int lanebase = (m & 7) << 2;
#pragma unroll
            for (int e = 0; e < 4; e++) {
                int k = kq * 4 + e;
                int ks = k >> 3;
                int reg = rbit | (((k >> 2) & 1) << 1);
                Af[((mb * 4 + ks) << 7) + ((lanebase + (k & 3)) << 2) + reg] =
                    f2tf32(wv[e]);
            }
        }
#pragma unroll
        for (int i = 0; i < 4; i++) {
            int idx = i * 256 + tid;
            int k  = idx >> 5;
            int nq = idx & 31;
            float4 v = *(const float4*)(Xb + (size_t)(kc + k) * HW + nq * 4);
            uint4 t;
            t.x = f2tf32(v.x); t.y = f2tf32(v.y);
            t.z = f2tf32(v.z); t.w = f2tf32(v.w);
            *(uint4*)&Bs[k * BS_STRIDE + nq * 4] = t;
        }
        __syncthreads();

#pragma unroll
        for (int ks = 0; ks < 4; ks++) {
            uint32_t afr[4][4];
#pragma unroll
            for (int mb = 0; mb < 4; mb++) {
                int mbg = wm * 4 + mb;
                *(uint4*)afr[mb] =
                    *(uint4*)&Af[((mbg * 4 + ks) << 7) + (lane << 2)];
            }
            uint32_t bfr[4][2];
            const int krow = ks * 8 + (lane & 3);
            const int ncol = wn * 32 + (lane >> 2);
#pragma unroll
            for (int nb = 0; nb < 4; nb++) {
                bfr[nb][0] = Bs[krow * BS_STRIDE + ncol + nb * 8];
                bfr[nb][1] = Bs[(krow + 4) * BS_STRIDE + ncol + nb * 8];
            }
#pragma unroll
            for (int mb = 0; mb < 4; mb++)
#pragma unroll
                for (int nb = 0; nb < 4; nb++)
                    mma1688(acc[mb][nb], afr[mb], bfr[nb][0], bfr[nb][1]);
        }
    }

    float* Yb = Y + (size_t)bb * IMG + p0;
    const int rl = lane >> 2;
    const int cl = (lane & 3) * 2;
#pragma unroll
    for (int mb = 0; mb < 4; mb++) {
        int mrow = m0 + wm * 64 + mb * 16 + rl;
#pragma unroll
        for (int nb = 0; nb < 4; nb++) {
            int ncol = wn * 32 + nb * 8 + cl;
            float2 v0 = make_float2(acc[mb][nb][0], acc[mb][nb][1]);
            float2 v1 = make_float2(acc[mb][nb][2], acc[mb][nb][3]);
            *(float2*)(Yb + (size_t)mrow * HW + ncol)       = v0;
            *(float2*)(Yb + (size_t)(mrow + 8) * HW + ncol) = v1;
        }
    }
}

// ---------------------------------------------------------------------------
// Kernel 2: GroupNorm statistics (unchanged).
// ---------------------------------------------------------------------------
__global__ void __launch_bounds__(256) stats_kernel()
{
    const int id  = blockIdx.x;
    const int t   = id >> 8;
    const int b   = (id >> 5) & 7;
    const int g   = id & 31;
    const int tid = threadIdx.x;

    const float* src = (t ? g_kraw : g_qraw) + (size_t)b * IMG + (size_t)g * (GSZ * HW);
    const float4* p4 = (const float4*)src;

    float s = 0.f, sq = 0.f;
#pragma unroll 4
    for (int i = 0; i < 128; i++) {
        float4 v = p4[(size_t)i * 256 + tid];
        s  += v.x + v.y + v.z + v.w;
        sq += v.x * v.x + v.y * v.y + v.z * v.z + v.w * v.w;
    }

    __shared__ float rs[256], rq[256];
    rs[tid] = s; rq[tid] = sq;
    __syncthreads();
    for (int o = 128; o > 0; o >>= 1) {
        if (tid < o) { rs[tid] += rs[tid + o]; rq[tid] += rq[tid + o]; }
        __syncthreads();
    }
    if (tid == 0) {
        const float invN = 1.f / (float)(GSZ * HW);
        float m   = rs[0] * invN;
        float var = rq[0] * invN - m * m;
        g_mean[id] = m;
        g_rstd[id] = rsqrtf(var + EPS);
    }
}

// ---------------------------------------------------------------------------
// Kernel 3: windowed attention via mma.sync tf32, channel-streamed.
// One CTA per 8x8 window; smem 34 KB static; 8 warps.
//   Phase S : loop 8 channel-chunks of 32; S[64x64] += Qc^T Kc  (mma)
//   softmax : in smem
//   Phase PV: loop 8 channel-chunks; out[64, chunk] = P * Kc^T (mma),
//             K re-streamed from gmem, epilogue + residual per chunk.
// ---------------------------------------------------------------------------
#define ST 68

__global__ void __launch_bounds__(256) attn_mma(
    const float* __restrict__ xlo, float* __restrict__ outp,
    const float* __restrict__ gq, const float* __restrict__ bq,
    const float* __restrict__ gk, const float* __restrict__ bk)
{
    __shared__ uint32_t sQ[32 * ST];   // chunk, [ch_local][px]; tf32 bits
    __shared__ uint32_t sK[32 * ST];   // chunk, [ch_local][px]; tf32 bits
    __shared__ float    sP[64 * ST];   // S / P matrix [i][j]

    const int tid  = threadIdx.x;
    const int wid  = tid >> 5;
    const int lane = tid & 31;

    const int bb  = blockIdx.x >> 8;
    const int rem = blockIdx.x & 255;
    const int base_px = ((rem >> 4) << 3) * 128 + ((rem & 15) << 3);

    const float* qb = g_qraw + (size_t)bb * IMG;
    const float* kb = g_kraw + (size_t)bb * IMG;

    // staging mapping: each thread owns (channel_local, patch_row)
    const int scl = tid >> 3;    // 0..31
    const int sp1 = tid & 7;     // 0..7

    // ---------------- Phase S ----------------
    const int wm = wid & 3;      // m-tile: rows wm*16..+15
    const int wn = wid >> 2;     // n half: cols wn*32..+31

    float acc[4][4];
#pragma unroll
    for (int i = 0; i < 4; i++)
#pragma unroll
        for (int j = 0; j < 4; j++) acc[i][j] = 0.f;

#pragma unroll 1
    for (int cc = 0; cc < 8; cc++) {
        __syncthreads();   // previous chunk consumed
        {
            const int c = cc * 32 + scl;
            const int g = c >> 3;
            const size_t ga = (size_t)c * HW + base_px + sp1 * 128;
            const int pix = sp1 * 8;
            // q
            {
                float a = g_rstd[bb * 32 + g] * gq[c];
                float d = fmaf(-g_mean[bb * 32 + g], a, bq[c]);
                float4 v0 = *(const float4*)(qb + ga);
                float4 v1 = *(const float4*)(qb + ga + 4);
                uint4 t0, t1;
                t0.x = f2tf32(fmaf(v0.x, a, d)); t0.y = f2tf32(fmaf(v0.y, a, d));
                t0.z = f2tf32(fmaf(v0.z, a, d)); t0.w = f2tf32(fmaf(v0.w, a, d));
                t1.x = f2tf32(fmaf(v1.x, a, d)); t1.y = f2tf32(fmaf(v1.y, a, d));
                t1.z = f2tf32(fmaf(v1.z, a, d)); t1.w = f2tf32(fmaf(v1.w, a, d));
                *(uint4*)&sQ[scl * ST + pix]     = t0;
                *(uint4*)&sQ[scl * ST + pix + 4] = t1;
            }
            // k
            {
                float a = g_rstd[256 + bb * 32 + g] * gk[c];
                float d = fmaf(-g_mean[256 + bb * 32 + g], a, bk[c]);
                float4 v0 = *(const float4*)(kb + ga);
                float4 v1 = *(const float4*)(kb + ga + 4);
                uint4 t0, t1;
                t0.x = f2tf32(fmaf(v0.x, a, d)); t0.y = f2tf32(fmaf(v0.y, a, d));
                t0.z = f2tf32(fmaf(v0.z, a, d)); t0.w = f2tf32(fmaf(v0.w, a, d));
                t1.x = f2tf32(fmaf(v1.x, a, d)); t1.y = f2tf32(fmaf(v1.y, a, d));
                t1.z = f2tf32(fmaf(v1.z, a, d)); t1.w = f2tf32(fmaf(v1.w, a, d));
                *(uint4*)&sK[scl * ST + pix]     = t0;
                *(uint4*)&sK[scl * ST + pix + 4] = t1;
            }
        }
        __syncthreads();

        // mma: S[wm*16.., wn*32..] += Qc^T Kc  (A[m=i][k=c]=Q[c][i])
#pragma unroll
        for (int ks = 0; ks < 4; ks++) {
            const int k0 = ks * 8 + (lane & 3);
            const int mrow = wm * 16 + (lane >> 2);
            uint32_t a[4];
            a[0] = sQ[k0 * ST + mrow];
            a[1] = sQ[k0 * ST + mrow + 8];
            a[2] = sQ[(k0 + 4) * ST + mrow];
            a[3] = sQ[(k0 + 4) * ST + mrow + 8];
#pragma unroll
            for (int nb = 0; nb < 4; nb++) {
                const int ncol = wn * 32 + nb * 8 + (lane >> 2);
                uint32_t b0 = sK[k0 * ST + ncol];
                uint32_t b1 = sK[(k0 + 4) * ST + ncol];
                mma1688(acc[nb], a, b0, b1);
            }
        }
    }
    __syncthreads();

    // write S (scaled by 1/sqrt(256)=1/16) to sP
    {
        const int r0 = wm * 16 + (lane >> 2);
        const int c0 = wn * 32 + (lane & 3) * 2;
#pragma unroll
        for (int nb = 0; nb < 4; nb++) {
            *(float2*)&sP[r0 * ST + c0 + nb * 8] =
                make_float2(acc[nb][0] * 0.0625f, acc[nb][1] * 0.0625f);
            *(float2*)&sP[(r0 + 8) * ST + c0 + nb * 8] =
                make_float2(acc[nb][2] * 0.0625f, acc[nb][3] * 0.0625f);
        }
    }
    __syncthreads();

    // ---------------- softmax on sP rows (4 threads per row) ----------------
    {
        const int row = tid >> 2;
        const int qq  = tid & 3;
        float v[16];
        *(float4*)&v[0]  = *(float4*)&sP[row * ST + qq * 16];
        *(float4*)&v[4]  = *(float4*)&sP[row * ST + qq * 16 + 4];
        *(float4*)&v[8]  = *(float4*)&sP[row * ST + qq * 16 + 8];
        *(float4*)&v[12] = *(float4*)&sP[row * ST + qq * 16 + 12];
        float mx = v[0];
#pragma unroll
        for (int i = 1; i < 16; i++) mx = fmaxf(mx, v[i]);
        mx = fmaxf(mx, __shfl_xor_sync(0xffffffffu, mx, 1));
        mx = fmaxf(mx, __shfl_xor_sync(0xffffffffu, mx, 2));
        float sum = 0.f;
#pragma unroll
        for (int i = 0; i < 16; i++) { v[i] = __expf(v[i] - mx); sum += v[i]; }
        sum += __shfl_xor_sync(0xffffffffu, sum, 1);
        sum += __shfl_xor_sync(0xffffffffu, sum, 2);
        float inv = 1.f / sum;
        uint32_t* sPu = (uint32_t*)sP;
#pragma unroll
        for (int i = 0; i < 16; i++)
            sPu[row * ST + qq * 16 + i] = f2tf32(v[i] * inv);
    }
    __syncthreads();

    // ---------------- Phase PV ----------------
    // out[i][c] = sum_j P[i][j] * Kn[c][j]; chunk over c.
    const uint32_t* sPu = (const uint32_t*)sP;
    uint32_t* sO = sQ;   // reuse sQ region: [ch_local][px] fp32 bits

#pragma unroll 1
    for (int cc = 0; cc < 8; cc++) {
        if (cc) __syncthreads();   // sK & sO consumed
        {
            const int c = cc * 32 + scl;
            const int g = c >> 3;
            const size_t ga = (size_t)c * HW + base_px + sp1 * 128;
            const int pix = sp1 * 8;
            float a = g_rstd[256 + bb * 32 + g] * gk[c];
            float d = fmaf(-g_mean[256 + bb * 32 + g], a, bk[c]);
            float4 v0 = *(const float4*)(kb + ga);
            float4 v1 = *(const float4*)(kb + ga + 4);
            uint4 t0, t1;
            t0.x = f2tf32(fmaf(v0.x, a, d)); t0.y = f2tf32(fmaf(v0.y, a, d));
            t0.z = f2tf32(fmaf(v0.z, a, d)); t0.w = f2tf32(fmaf(v0.w, a, d));
            t1.x = f2tf32(fmaf(v1.x, a, d)); t1.y = f2tf32(fmaf(v1.y, a, d));
            t1.z = f2tf32(fmaf(v1.z, a, d)); t1.w = f2tf32(fmaf(v1.w, a, d));
            *(uint4*)&sK[scl * ST + pix]     = t0;
            *(uint4*)&sK[scl * ST + pix + 4] = t1;
        }
        __syncthreads();

        float acc2[2][4];
#pragma unroll
        for (int nb = 0; nb < 2; nb++)
#pragma unroll
            for (int r = 0; r < 4; r++) acc2[nb][r] = 0.f;

#pragma unroll
        for (int ks = 0; ks < 8; ks++) {
            const int k0 = ks * 8 + (lane & 3);         // j (pixel)
            const int mrow = wm * 16 + (lane >> 2);
            uint32_t a[4];
            a[0] = sPu[mrow * ST + k0];
            a[1] = sPu[(mrow + 8) * ST + k0];
            a[2] = sPu[mrow * ST + k0 + 4];
            a[3] = sPu[(mrow + 8) * ST + k0 + 4];
#pragma unroll
            for (int nb = 0; nb < 2; nb++) {
                const int nch = wn * 16 + nb * 8 + (lane >> 2);  // ch_local
                uint32_t b0 = sK[nch * ST + k0];
                uint32_t b1 = sK[nch * ST + k0 + 4];
                mma1688(acc2[nb], a, b0, b1);
            }
        }

        // stage out-chunk to sO [ch_local][px]
        {
            const int px = wm * 16 + (lane >> 2);
#pragma unroll
            for (int nb = 0; nb < 2; nb++) {
                const int chl = wn * 16 + nb * 8 + (lane & 3) * 2;
                float* sOf = (float*)sO;
                sOf[chl * ST + px]           = acc2[nb][0];
                sOf[(chl + 1) * ST + px]     = acc2[nb][1];
                sOf[chl * ST + px + 8]       = acc2[nb][2];
                sOf[(chl + 1) * ST + px + 8] = acc2[nb][3];
            }
        }
        __syncthreads();

        // gmem write + residual: 32 ch x 64 px = 512 float4
        const float* sOf = (const float*)sO;
#pragma unroll
        for (int i = 0; i < 2; i++) {
            int seg = i * 256 + tid;       // 0..511
            int c_l = seg >> 4;            // 0..31
            int r4  = seg & 15;
            int p1w = r4 >> 1;
            int h   = (r4 & 1) * 4;
            size_t ga = (size_t)bb * IMG + (size_t)(cc * 32 + c_l) * HW +
                        base_px + p1w * 128 + h;
            float4 o = *(const float4*)&sOf[c_l * ST + p1w * 8 + h];
            float4 x = *(const float4*)(xlo + ga);
            o.x += x.x; o.y += x.y; o.z += x.z; o.w += x.w;
            *(float4*)(outp + ga) = o;
        }
    }
}

// ---------------------------------------------------------------------------
// Launcher
// ---------------------------------------------------------------------------
extern "C" void kernel_launch(void* const* d_in, const int* in_sizes, int n_in,
                              void* d_out, int out_size)
{
    const float* x_low  = (const float*)d_in[0];
    const float* x_high = (const float*)d_in[1];
    const float* wq     = (const float*)d_in[2];
    const float* wk     = (const float*)d_in[3];
    const float* gq     = (const float*)d_in[4];
    const float* bq     = (const float*)d_in[5];
    const float* gk     = (const float*)d_in[6];
    const float* bk     = (const float*)d_in[7];
    float* outp = (float*)d_out;

    proj_mma<<<dim3(2, 1024, 2), 256>>>(wq, wk, x_low, x_high);
    stats_kernel<<<512, 256>>>();
    attn_mma<<<2048, 256>>>(x_low, outp, gq, bq, gk, bk);
}

// round 5
// speedup vs baseline: 2.5525x; 1.2239x over previous
#include <cuda_runtime.h>
#include <cstdint>

// ---------------------------------------------------------------------------
// Problem constants
// ---------------------------------------------------------------------------
#define BATCH   8
#define CH      256
#define HW      16384
#define IMG     (CH * HW)
#define GROUPS  32
#define GSZ     (CH / GROUPS)
#define NPIX    64
#define EPS     1e-5f

static __device__ float g_qraw[(size_t)BATCH * IMG];
static __device__ float g_kraw[(size_t)BATCH * IMG];
static __device__ float g_mean[2 * BATCH * GROUPS];
static __device__ float g_rstd[2 * BATCH * GROUPS];
// Pre-permuted A operand fragments (tf32, mma layout):
// [t(2)][mt(2)][chunk(8)][mbg(8)*ks(4)][lane(32)][reg(4)]
static __device__ uint32_t g_afrag[131072];

// ---------------------------------------------------------------------------
// tf32 / async helpers (legacy mma.sync path — plain sm_103 PTX target)
// ---------------------------------------------------------------------------
__device__ __forceinline__ uint32_t f2tf32(float f) {
    uint32_t r;
    asm("cvt.rna.tf32.f32 %0, %1;" : "=r"(r) : "f"(f));
    return r;
}

__device__ __forceinline__ void mma1688(float d[4], const uint32_t a[4],
                                        uint32_t b0, uint32_t b1) {
    asm volatile(
        "mma.sync.aligned.m16n8k8.row.col.f32.tf32.tf32.f32 "
        "{%0,%1,%2,%3}, {%4,%5,%6,%7}, {%8,%9}, {%0,%1,%2,%3};"
        : "+f"(d[0]), "+f"(d[1]), "+f"(d[2]), "+f"(d[3])
        : "r"(a[0]), "r"(a[1]), "r"(a[2]), "r"(a[3]), "r"(b0), "r"(b1));
}

__device__ __forceinline__ uint32_t smem_u32(const void* p) {
    uint32_t a;
    asm("{ .reg .u64 t; cvta.to.shared.u64 t, %1; cvt.u32.u64 %0, t; }"
        : "=r"(a) : "l"(p));
    return a;
}

__device__ __forceinline__ void cpa16(uint32_t dst, const void* src) {
    asm volatile("cp.async.cg.shared.global [%0], [%1], 16;"
                 :: "r"(dst), "l"(src));
}
#define CPA_COMMIT() asm volatile("cp.async.commit_group;" ::: "memory")
#define CPA_WAIT(N)  asm volatile("cp.async.wait_group %0;" :: "n"(N) : "memory")

// ---------------------------------------------------------------------------
// Kernel 0: build fragment-ordered tf32 A operand (runs once per launch; ~3us)
// ---------------------------------------------------------------------------
__global__ void __launch_bounds__(256) prep_afrag(
    const float* __restrict__ wq, const float* __restrict__ wk)
{
    int idx = blockIdx.x * 256 + threadIdx.x;   // 0 .. 131071
    int reg  = idx & 3;
    int lane = (idx >> 2) & 31;
    int ks   = (idx >> 7) & 3;
    int mbg  = (idx >> 9) & 7;
    int c    = (idx >> 12) & 7;
    int mt   = (idx >> 15) & 1;
    int t    = (idx >> 16) & 1;

    int m = mt * 128 + mbg * 16 + (reg & 1) * 8 + (lane >> 2);
    int k = c * 32 + ks * 8 + ((reg >> 1) & 1) * 4 + (lane & 3);
    const float* W = t ? wk : wq;
    g_afrag[idx] = f2tf32(W[m * CH + k]);
}

// ---------------------------------------------------------------------------
// Kernel 1: projection GEMM, cp.async double-buffered, pre-permuted A.
// D[m,n] = sum_k W[m,k] * X[k,n].  CTA tile 128m x 128n, K chunks of 32.
// grid = (2 m-tiles, 1024 pixel-tiles, 2 tensors).
// smem (floats): A0 @0, A1 @4096, B0 @8192, B1 @12416 ; total 16640 = 66560 B
// ---------------------------------------------------------------------------
#define BS_STRIDE 132
#define PR_A(buf)  ((buf) * 4096)
#define PR_B(buf)  (8192 + (buf) * (32 * BS_STRIDE))
#define PR_SMEM_BYTES ((8192 + 2 * 32 * BS_STRIDE) * 4)

__global__ void __launch_bounds__(256, 2) proj_mma(
    const float* __restrict__ xlo, const float* __restrict__ xhi)
{
    extern __shared__ __align__(16) uint32_t smu[];
    const uint32_t sbase = smem_u32(smu);

    const int tid  = threadIdx.x;
    const int wid  = tid >> 5;
    const int lane = tid & 31;

    const int mt = blockIdx.x;
    const int tz = blockIdx.z;
    const float* X = tz ? xhi : xlo;
    float*       Y = tz ? g_kraw : g_qraw;

    const int bb = blockIdx.y >> 7;
    const int p0 = (blockIdx.y & 127) << 7;
    const int m0 = mt << 7;

    const float* Xb = X + (size_t)bb * IMG + p0;
    const uint32_t* Ag = g_afrag + (size_t)(tz * 2 + mt) * 32768;

    const int wm = wid >> 2;
    const int wn = wid & 3;

    float acc[4][4][4];
#pragma unroll
    for (int i = 0; i < 4; i++)
#pragma unroll
        for (int j = 0; j < 4; j++)
#pragma unroll
            for (int r = 0; r < 4; r++) acc[i][j][r] = 0.f;

    // ---- prefetch chunk 0 into buffer 0 ----
#pragma unroll
    for (int i = 0; i < 4; i++) {
        int idx = i * 256 + tid;
        cpa16(sbase + (PR_A(0) + idx * 4) * 4, Ag + idx * 4);
        int k = idx >> 5, nq = idx & 31;
        cpa16(sbase + (PR_B(0) + k * BS_STRIDE + nq * 4) * 4,
              Xb + (size_t)k * HW + nq * 4);
    }
    CPA_COMMIT();

#pragma unroll 1
    for (int c = 0; c < 8; c++) {
        const int buf = c & 1;

        if (c < 7) {   // prefetch next chunk into other buffer
            const int kc = (c + 1) << 5;
            const uint32_t* Agc = Ag + (c + 1) * 4096;
#pragma unroll
            for (int i = 0; i < 4; i++) {
                int idx = i * 256 + tid;
                cpa16(sbase + (PR_A(buf ^ 1) + idx * 4) * 4, Agc + idx * 4);
                int k = idx >> 5, nq = idx & 31;
                cpa16(sbase + (PR_B(buf ^ 1) + k * BS_STRIDE + nq * 4) * 4,
                      Xb + (size_t)(kc + k) * HW + nq * 4);
            }
            CPA_COMMIT();
            CPA_WAIT(1);
        } else {
            CPA_WAIT(0);
        }
        __syncthreads();

        const uint32_t* Ab = smu + PR_A(buf);
        const uint32_t* Bb = smu + PR_B(buf);

#pragma unroll
        for (int ks = 0; ks < 4; ks++) {
            uint32_t afr[4][4];
#pragma unroll
            for (int mb = 0; mb < 4; mb++) {
                int mbg = wm * 4 + mb;
                *(uint4*)afr[mb] = *(const uint4*)&Ab[((mbg * 4 + ks) << 7) + (lane << 2)];
            }
            uint32_t bfr[4][2];
            const int krow = ks * 8 + (lane & 3);
            const int ncol = wn * 32 + (lane >> 2);
#pragma unroll
            for (int nb = 0; nb < 4; nb++) {
                bfr[nb][0] = Bb[krow * BS_STRIDE + ncol + nb * 8];
                bfr[nb][1] = Bb[(krow + 4) * BS_STRIDE + ncol + nb * 8];
            }
#pragma unroll
            for (int mb = 0; mb < 4; mb++)
#pragma unroll
                for (int nb = 0; nb < 4; nb++)
                    mma1688(acc[mb][nb], afr[mb], bfr[nb][0], bfr[nb][1]);
        }
        __syncthreads();   // buffer consumed; safe to overwrite next iter
    }

    // ---- epilogue ----
    float* Yb = Y + (size_t)bb * IMG + p0;
    const int rl = lane >> 2;
    const int cl = (lane & 3) * 2;
#pragma unroll
    for (int mb = 0; mb < 4; mb++) {
        int mrow = m0 + wm * 64 + mb * 16 + rl;
#pragma unroll
        for (int nb = 0; nb < 4; nb++) {
            int ncol = wn * 32 + nb * 8 + cl;
            float2 v0 = make_float2(acc[mb][nb][0], acc[mb][nb][1]);
            float2 v1 = make_float2(acc[mb][nb][2], acc[mb][nb][3]);
            *(float2*)(Yb + (size_t)mrow * HW + ncol)       = v0;
            *(float2*)(Yb + (size_t)(mrow + 8) * HW + ncol) = v1;
        }
    }
}

// ---------------------------------------------------------------------------
// Kernel 2: GroupNorm statistics (unchanged).
// ---------------------------------------------------------------------------
__global__ void __launch_bounds__(256) stats_kernel()
{
    const int id  = blockIdx.x;
    const int t   = id >> 8;
    const int b   = (id >> 5) & 7;
    const int g   = id & 31;
    const int tid = threadIdx.x;

    const float* src = (t ? g_kraw : g_qraw) + (size_t)b * IMG + (size_t)g * (GSZ * HW);
    const float4* p4 = (const float4*)src;

    float s = 0.f, sq = 0.f;
#pragma unroll 4
    for (int i = 0; i < 128; i++) {
        float4 v = p4[(size_t)i * 256 + tid];
        s  += v.x + v.y + v.z + v.w;
        sq += v.x * v.x + v.y * v.y + v.z * v.z + v.w * v.w;
    }

    __shared__ float rs[256], rq[256];
    rs[tid] = s; rq[tid] = sq;
    __syncthreads();
    for (int o = 128; o > 0; o >>= 1) {
        if (tid < o) { rs[tid] += rs[tid + o]; rq[tid] += rq[tid + o]; }
        __syncthreads();
    }
    if (tid == 0) {
        const float invN = 1.f / (float)(GSZ * HW);
        float m   = rs[0] * invN;
        float var = rq[0] * invN - m * m;
        g_mean[id] = m;
        g_rstd[id] = rsqrtf(var + EPS);
    }
}

// ---------------------------------------------------------------------------
// Kernel 3: windowed attention via mma.sync tf32, channel-streamed (unchanged).
// ---------------------------------------------------------------------------
#define ST 68

__global__ void __launch_bounds__(256) attn_mma(
    const float* __restrict__ xlo, float* __restrict__ outp,
    const float* __restrict__ gq, const float* __restrict__ bq,
    const float* __restrict__ gk, const float* __restrict__ bk)
{
    __shared__ uint32_t sQ[32 * ST];
    __shared__ uint32_t sK[32 * ST];
    __shared__ float    sP[64 * ST];

    const int tid  = threadIdx.x;
    const int wid  = tid >> 5;
    const int lane = tid & 31;

    const int bb  = blockIdx.x >> 8;
    const int rem = blockIdx.x & 255;
    const int base_px = ((rem >> 4) << 3) * 128 + ((rem & 15) << 3);

    const float* qb = g_qraw + (size_t)bb * IMG;
    const float* kb = g_kraw + (size_t)bb * IMG;

    const int scl = tid >> 3;
    const int sp1 = tid & 7;

    const int wm = wid & 3;
    const int wn = wid >> 2;

    float acc[4][4];
#pragma unroll
    for (int i = 0; i < 4; i++)
#pragma unroll
        for (int j = 0; j < 4; j++) acc[i][j] = 0.f;

#pragma unroll 1
    for (int cc = 0; cc < 8; cc++) {
        __syncthreads();
        {
            const int c = cc * 32 + scl;
            const int g = c >> 3;
            const size_t ga = (size_t)c * HW + base_px + sp1 * 128;
            const int pix = sp1 * 8;
            {
                float a = g_rstd[bb * 32 + g] * gq[c];
                float d = fmaf(-g_mean[bb * 32 + g], a, bq[c]);
                float4 v0 = *(const float4*)(qb + ga);
                float4 v1 = *(const float4*)(qb + ga + 4);
                uint4 t0, t1;
                t0.x = f2tf32(fmaf(v0.x, a, d)); t0.y = f2tf32(fmaf(v0.y, a, d));
                t0.z = f2tf32(fmaf(v0.z, a, d)); t0.w = f2tf32(fmaf(v0.w, a, d));
                t1.x = f2tf32(fmaf(v1.x, a, d)); t1.y = f2tf32(fmaf(v1.y, a, d));
                t1.z = f2tf32(fmaf(v1.z, a, d)); t1.w = f2tf32(fmaf(v1.w, a, d));
                *(uint4*)&sQ[scl * ST + pix]     = t0;
                *(uint4*)&sQ[scl * ST + pix + 4] = t1;
            }
            {
                float a = g_rstd[256 + bb * 32 + g] * gk[c];
                float d = fmaf(-g_mean[256 + bb * 32 + g], a, bk[c]);
                float4 v0 = *(const float4*)(kb + ga);
                float4 v1 = *(const float4*)(kb + ga + 4);
                uint4 t0, t1;
                t0.x = f2tf32(fmaf(v0.x, a, d)); t0.y = f2tf32(fmaf(v0.y, a, d));
                t0.z = f2tf32(fmaf(v0.z, a, d)); t0.w = f2tf32(fmaf(v0.w, a, d));
                t1.x = f2tf32(fmaf(v1.x, a, d)); t1.y = f2tf32(fmaf(v1.y, a, d));
                t1.z = f2tf32(fmaf(v1.z, a, d)); t1.w = f2tf32(fmaf(v1.w, a, d));
                *(uint4*)&sK[scl * ST + pix]     = t0;
                *(uint4*)&sK[scl * ST + pix + 4] = t1;
            }
        }
        __syncthreads();

#pragma unroll
        for (int ks = 0; ks < 4; ks++) {
            const int k0 = ks * 8 + (lane & 3);
            const int mrow = wm * 16 + (lane >> 2);
            uint32_t a[4];
            a[0] = sQ[k0 * ST + mrow];
            a[1] = sQ[k0 * ST + mrow + 8];
            a[2] = sQ[(k0 + 4) * ST + mrow];
            a[3] = sQ[(k0 + 4) * ST + mrow + 8];
#pragma unroll
            for (int nb = 0; nb < 4; nb++) {
                const int ncol = wn * 32 + nb * 8 + (lane >> 2);
                uint32_t b0 = sK[k0 * ST + ncol];
                uint32_t b1 = sK[(k0 + 4) * ST + ncol];
                mma1688(acc[nb], a, b0, b1);
            }
        }
    }
    __syncthreads();

    {
        const int r0 = wm * 16 + (lane >> 2);
        const int c0 = wn * 32 + (lane & 3) * 2;
#pragma unroll
        for (int nb = 0; nb < 4; nb++) {
            *(float2*)&sP[r0 * ST + c0 + nb * 8] =
                make_float2(acc[nb][0] * 0.0625f, acc[nb][1] * 0.0625f);
            *(float2*)&sP[(r0 + 8) * ST + c0 + nb * 8] =
                make_float2(acc[nb][2] * 0.0625f, acc[nb][3] * 0.0625f);
        }
    }
    __syncthreads();

    {
        const int row = tid >> 2;
        const int qq  = tid & 3;
        float v[16];
        *(float4*)&v[0]  = *(float4*)&sP[row * ST + qq * 16];
        *(float4*)&v[4]  = *(float4*)&sP[row * ST + qq * 16 + 4];
        *(float4*)&v[8]  = *(float4*)&sP[row * ST + qq * 16 + 8];
        *(float4*)&v[12] = *(float4*)&sP[row * ST + qq * 16 + 12];
        float mx = v[0];
#pragma unroll
        for (int i = 1; i < 16; i++) mx = fmaxf(mx, v[i]);
        mx = fmaxf(mx, __shfl_xor_sync(0xffffffffu, mx, 1));
        mx = fmaxf(mx, __shfl_xor_sync(0xffffffffu, mx, 2));
        float sum = 0.f;
#pragma unroll
        for (int i = 0; i < 16; i++) { v[i] = __expf(v[i] - mx); sum += v[i]; }
        sum += __shfl_xor_sync(0xffffffffu, sum, 1);
        sum += __shfl_xor_sync(0xffffffffu, sum, 2);
        float inv = 1.f / sum;
        uint32_t* sPu = (uint32_t*)sP;
#pragma unroll
        for (int i = 0; i < 16; i++)
            sPu[row * ST + qq * 16 + i] = f2tf32(v[i] * inv);
    }
    __syncthreads();

    const uint32_t* sPu = (const uint32_t*)sP;
    uint32_t* sO = sQ;

#pragma unroll 1
    for (int cc = 0; cc < 8; cc++) {
        if (cc) __syncthreads();
        {
            const int c = cc * 32 + scl;
            const int g = c >> 3;
            const size_t ga = (size_t)c * HW + base_px + sp1 * 128;
            const int pix = sp1 * 8;
            float a = g_rstd[256 + bb * 32 + g] * gk[c];
            float d = fmaf(-g_mean[256 + bb * 32 + g], a, bk[c]);
            float4 v0 = *(const float4*)(kb + ga);
            float4 v1 = *(const float4*)(kb + ga + 4);
            uint4 t0, t1;
            t0.x = f2tf32(fmaf(v0.x, a, d)); t0.y = f2tf32(fmaf(v0.y, a, d));
            t0.z = f2tf32(fmaf(v0.z, a, d)); t0.w = f2tf32(fmaf(v0.w, a, d));
            t1.x = f2tf32(fmaf(v1.x, a, d)); t1.y = f2tf32(fmaf(v1.y, a, d));
            t1.z = f2tf32(fmaf(v1.z, a, d)); t1.w = f2tf32(fmaf(v1.w, a, d));
            *(uint4*)&sK[scl * ST + pix]     = t0;
            *(uint4*)&sK[scl * ST + pix + 4] = t1;
        }
        __syncthreads();

        float acc2[2][4];
#pragma unroll
        for (int nb = 0; nb < 2; nb++)
#pragma unroll
            for (int r = 0; r < 4; r++) acc2[nb][r] = 0.f;

#pragma unroll
        for (int ks = 0; ks < 8; ks++) {
            const int k0 = ks * 8 + (lane & 3);
            const int mrow = wm * 16 + (lane >> 2);
            uint32_t a[4];
            a[0] = sPu[mrow * ST + k0];
            a[1] = sPu[(mrow + 8) * ST + k0];
            a[2] = sPu[mrow * ST + k0 + 4];
            a[3] = sPu[(mrow + 8) * ST + k0 + 4];
#pragma unroll
            for (int nb = 0; nb < 2; nb++) {
                const int nch = wn * 16 + nb * 8 + (lane >> 2);
                uint32_t b0 = sK[nch * ST + k0];
                uint32_t b1 = sK[nch * ST + k0 + 4];
                mma1688(acc2[nb], a, b0, b1);
            }
        }

        {
            const int px = wm * 16 + (lane >> 2);
#pragma unroll
            for (int nb = 0; nb < 2; nb++) {
                const int chl = wn * 16 + nb * 8 + (lane & 3) * 2;
                float* sOf = (float*)sO;
                sOf[chl * ST + px]           = acc2[nb][0];
                sOf[(chl + 1) * ST + px]     = acc2[nb][1];
                sOf[chl * ST + px + 8]       = acc2[nb][2];
                sOf[(chl + 1) * ST + px + 8] = acc2[nb][3];
            }
        }
        __syncthreads();

        const float* sOf = (const float*)sO;
#pragma unroll
        for (int i = 0; i < 2; i++) {
            int seg = i * 256 + tid;
            int c_l = seg >> 4;
            int r4  = seg & 15;
            int p1w = r4 >> 1;
            int h   = (r4 & 1) * 4;
            size_t ga = (size_t)bb * IMG + (size_t)(cc * 32 + c_l) * HW +
                        base_px + p1w * 128 + h;
            float4 o = *(const float4*)&sOf[c_l * ST + p1w * 8 + h];
            float4 x = *(const float4*)(xlo + ga);
            o.x += x.x; o.y += x.y; o.z += x.z; o.w += x.w;
            *(float4*)(outp + ga) = o;
        }
    }
}

// ---------------------------------------------------------------------------
// Launcher
// ---------------------------------------------------------------------------
extern "C" void kernel_launch(void* const* d_in, const int* in_sizes, int n_in,
                              void* d_out, int out_size)
{
    const float* x_low  = (const float*)d_in[0];
    const float* x_high = (const float*)d_in[1];
    const float* wq     = (const float*)d_in[2];
    const float* wk     = (const float*)d_in[3];
    const float* gq     = (const float*)d_in[4];
    const float* bq     = (const float*)d_in[5];
    const float* gk     = (const float*)d_in[6];
    const float* bk     = (const float*)d_in[7];
    float* outp = (float*)d_out;

    prep_afrag<<<512, 256>>>(wq, wk);

    cudaFuncSetAttribute(proj_mma,
                         cudaFuncAttributeMaxDynamicSharedMemorySize,
                         PR_SMEM_BYTES);
    proj_mma<<<dim3(2, 1024, 2), 256, PR_SMEM_BYTES>>>(x_low, x_high);

    stats_kernel<<<512, 256>>>();
    attn_mma<<<2048, 256>>>(x_low, outp, gq, bq, gk, bk);
}

// round 6
// speedup vs baseline: 2.9663x; 1.1621x over previous
#include <cuda_runtime.h>
#include <cstdint>

// ---------------------------------------------------------------------------
// Problem constants
// ---------------------------------------------------------------------------
#define BATCH   8
#define CH      256
#define HW      16384
#define IMG     (CH * HW)
#define GROUPS  32
#define GSZ     (CH / GROUPS)
#define NPIX    64
#define EPS     1e-5f

// g_qraw/g_kraw use WINDOW-TILED pixel layout within each channel:
//   px' = window_id * 64 + (y&7)*8 + (x&7),  window_id = (y>>3)*16 + (x>>3)
static __device__ float g_qraw[(size_t)BATCH * IMG];
static __device__ float g_kraw[(size_t)BATCH * IMG];
static __device__ float g_mean[2 * BATCH * GROUPS];
static __device__ float g_rstd[2 * BATCH * GROUPS];
// Pre-permuted A operand fragments (tf32, mma layout)
static __device__ uint32_t g_afrag[131072];

// ---------------------------------------------------------------------------
// tf32 / async helpers (legacy mma.sync path — plain sm_103 PTX target)
// ---------------------------------------------------------------------------
__device__ __forceinline__ uint32_t f2tf32(float f) {
    uint32_t r;
    asm("cvt.rna.tf32.f32 %0, %1;" : "=r"(r) : "f"(f));
    return r;
}

__device__ __forceinline__ void mma1688(float d[4], const uint32_t a[4],
                                        uint32_t b0, uint32_t b1) {
    asm volatile(
        "mma.sync.aligned.m16n8k8.row.col.f32.tf32.tf32.f32 "
        "{%0,%1,%2,%3}, {%4,%5,%6,%7}, {%8,%9}, {%0,%1,%2,%3};"
        : "+f"(d[0]), "+f"(d[1]), "+f"(d[2]), "+f"(d[3])
        : "r"(a[0]), "r"(a[1]), "r"(a[2]), "r"(a[3]), "r"(b0), "r"(b1));
}

__device__ __forceinline__ uint32_t smem_u32(const void* p) {
    uint32_t a;
    asm("{ .reg .u64 t; cvta.to.shared.u64 t, %1; cvt.u32.u64 %0, t; }"
        : "=r"(a) : "l"(p));
    return a;
}

__device__ __forceinline__ void cpa16(uint32_t dst, const void* src) {
    asm volatile("cp.async.cg.shared.global [%0], [%1], 16;"
                 :: "r"(dst), "l"(src));
}
#define CPA_COMMIT() asm volatile("cp.async.commit_group;" ::: "memory")
#define CPA_WAIT(N)  asm volatile("cp.async.wait_group %0;" :: "n"(N) : "memory")

// ---------------------------------------------------------------------------
// Kernel 0: build fragment-ordered tf32 A operand
// ---------------------------------------------------------------------------
__global__ void __launch_bounds__(256) prep_afrag(
    const float* __restrict__ wq, const float* __restrict__ wk)
{
    int idx = blockIdx.x * 256 + threadIdx.x;
    int reg  = idx & 3;
    int lane = (idx >> 2) & 31;
    int ks   = (idx >> 7) & 3;
    int mbg  = (idx >> 9) & 7;
    int c    = (idx >> 12) & 7;
    int mt   = (idx >> 15) & 1;
    int t    = (idx >> 16) & 1;

    int m = mt * 128 + mbg * 16 + (reg & 1) * 8 + (lane >> 2);
    int k = c * 32 + ks * 8 + ((reg >> 1) & 1) * 4 + (lane & 3);
    const float* W = t ? wk : wq;
    g_afrag[idx] = f2tf32(W[m * CH + k]);
}

// ---------------------------------------------------------------------------
// Kernel 1: projection GEMM, cp.async double-buffered, pre-permuted A.
// Epilogue writes WINDOW-TILED layout.
// ---------------------------------------------------------------------------
#define BS_STRIDE 132
#define PR_A(buf)  ((buf) * 4096)
#define PR_B(buf)  (8192 + (buf) * (32 * BS_STRIDE))
#define PR_SMEM_BYTES ((8192 + 2 * 32 * BS_STRIDE) * 4)

__global__ void __launch_bounds__(256, 2) proj_mma(
    const float* __restrict__ xlo, const float* __restrict__ xhi)
{
    extern __shared__ __align__(16) uint32_t smu[];
    const uint32_t sbase = smem_u32(smu);

    const int tid  = threadIdx.x;
    const int wid  = tid >> 5;
    const int lane = tid & 31;

    const int mt = blockIdx.x;
    const int tz = blockIdx.z;
    const float* X = tz ? xhi : xlo;
    float*       Y = tz ? g_kraw : g_qraw;

    const int bb = blockIdx.y >> 7;
    const int yrow = blockIdx.y & 127;          // image row y
    const int p0 = yrow << 7;
    const int m0 = mt << 7;

    const float* Xb = X + (size_t)bb * IMG + p0;
    const uint32_t* Ag = g_afrag + (size_t)(tz * 2 + mt) * 32768;

    const int wm = wid >> 2;
    const int wn = wid & 3;

    float acc[4][4][4];
#pragma unroll
    for (int i = 0; i < 4; i++)
#pragma unroll
        for (int j = 0; j < 4; j++)
#pragma unroll
            for (int r = 0; r < 4; r++) acc[i][j][r] = 0.f;

#pragma unroll
    for (int i = 0; i < 4; i++) {
        int idx = i * 256 + tid;
        cpa16(sbase + (PR_A(0) + idx * 4) * 4, Ag + idx * 4);
        int k = idx >> 5, nq = idx & 31;
        cpa16(sbase + (PR_B(0) + k * BS_STRIDE + nq * 4) * 4,
              Xb + (size_t)k * HW + nq * 4);
    }
    CPA_COMMIT();

#pragma unroll 1
    for (int c = 0; c < 8; c++) {
        const int buf = c & 1;

        if (c < 7) {
            const int kc = (c + 1) << 5;
            const uint32_t* Agc = Ag + (c + 1) * 4096;
#pragma unroll
            for (int i = 0; i < 4; i++) {
                int idx = i * 256 + tid;
                cpa16(sbase + (PR_A(buf ^ 1) + idx * 4) * 4, Agc + idx * 4);
                int k = idx >> 5, nq = idx & 31;
                cpa16(sbase + (PR_B(buf ^ 1) + k * BS_STRIDE + nq * 4) * 4,
                      Xb + (size_t)(kc + k) * HW + nq * 4);
            }
            CPA_COMMIT();
            CPA_WAIT(1);
        } else {
            CPA_WAIT(0);
        }
        __syncthreads();

        const uint32_t* Ab = smu + PR_A(buf);
        const uint32_t* Bb = smu + PR_B(buf);

#pragma unroll
        for (int ks = 0; ks < 4; ks++) {
            uint32_t afr[4][4];
#pragma unroll
            for (int mb = 0; mb < 4; mb++) {
                int mbg = wm * 4 + mb;
                *(uint4*)afr[mb] = *(const uint4*)&Ab[((mbg * 4 + ks) << 7) + (lane << 2)];
            }
            uint32_t bfr[4][2];
            const int krow = ks * 8 + (lane & 3);
            const int ncol = wn * 32 + (lane >> 2);
#pragma unroll
            for (int nb = 0; nb < 4; nb++) {
                bfr[nb][0] = Bb[krow * BS_STRIDE + ncol + nb * 8];
                bfr[nb][1] = Bb[(krow + 4) * BS_STRIDE + ncol + nb * 8];
            }
#pragma unroll
            for (int mb = 0; mb < 4; mb++)
#pragma unroll
                for (int nb = 0; nb < 4; nb++)
                    mma1688(acc[mb][nb], afr[mb], bfr[nb][0], bfr[nb][1]);
        }
        __syncthreads();
    }

    // ---- epilogue: window-tiled store ----
    // pixel x = wn*32 + nb*8 + cl  ->  offset (wn*4+nb)*64 + cl + base2
    const int base2 = (yrow >> 3) * 1024 + (yrow & 7) * 8;
    float* Yb = Y + (size_t)bb * IMG + base2;
    const int rl = lane >> 2;
    const int cl = (lane & 3) * 2;
#pragma unroll
    for (int mb = 0; mb < 4; mb++) {
        int mrow = m0 + wm * 64 + mb * 16 + rl;
#pragma unroll
        for (int nb = 0; nb < 4; nb++) {
            int noff = (wn * 4 + nb) * 64 + cl;
            float2 v0 = make_float2(acc[mb][nb][0], acc[mb][nb][1]);
            float2 v1 = make_float2(acc[mb][nb][2], acc[mb][nb][3]);
            *(float2*)(Yb + (size_t)mrow * HW + noff)       = v0;
            *(float2*)(Yb + (size_t)(mrow + 8) * HW + noff) = v1;
        }
    }
}

// ---------------------------------------------------------------------------
// Kernel 2: GroupNorm statistics (layout-invariant; unchanged).
// ---------------------------------------------------------------------------
__global__ void __launch_bounds__(256) stats_kernel()
{
    const int id  = blockIdx.x;
    const int t   = id >> 8;
    const int b   = (id >> 5) & 7;
    const int g   = id & 31;
    const int tid = threadIdx.x;

    const float* src = (t ? g_kraw : g_qraw) + (size_t)b * IMG + (size_t)g * (GSZ * HW);
    const float4* p4 = (const float4*)src;

    float s = 0.f, sq = 0.f;
#pragma unroll 4
    for (int i = 0; i < 128; i++) {
        float4 v = p4[(size_t)i * 256 + tid];
        s  += v.x + v.y + v.z + v.w;
        sq += v.x * v.x + v.y * v.y + v.z * v.z + v.w * v.w;
    }

    __shared__ float rs[256], rq[256];
    rs[tid] = s; rq[tid] = sq;
    __syncthreads();
    for (int o = 128; o > 0; o >>= 1) {
        if (tid < o) { rs[tid] += rs[tid + o]; rq[tid] += rq[tid + o]; }
        __syncthreads();
    }
    if (tid == 0) {
        const float invN = 1.f / (float)(GSZ * HW);
        float m   = rs[0] * invN;
        float var = rq[0] * invN - m * m;
        g_mean[id] = m;
        g_rstd[id] = rsqrtf(var + EPS);
    }
}

// ---------------------------------------------------------------------------
// Kernel 3: windowed attention (window-tiled q/k reads; contiguous 256B/ch).
// ---------------------------------------------------------------------------
#define ST 68

__global__ void __launch_bounds__(256) attn_mma(
    const float* __restrict__ xlo, float* __restrict__ outp,
    const float* __restrict__ gq, const float* __restrict__ bq,
    const float* __restrict__ gk, const float* __restrict__ bk)
{
    __shared__ uint32_t sQ[32 * ST];
    __shared__ uint32_t sK[32 * ST];
    __shared__ float    sP[64 * ST];

    const int tid  = threadIdx.x;
    const int wid  = tid >> 5;
    const int lane = tid & 31;

    const int bb  = blockIdx.x >> 8;
    const int wnd = blockIdx.x & 255;
    const int base_px = ((wnd >> 4) << 3) * 128 + ((wnd & 15) << 3);  // std layout (x_low/out)
    const int wbase = wnd * 64;                                       // tiled layout (q/k)

    const float* qb = g_qraw + (size_t)bb * IMG;
    const float* kb = g_kraw + (size_t)bb * IMG;

    const int scl = tid >> 3;
    const int sp1 = tid & 7;

    const int wm = wid & 3;
    const int wn = wid >> 2;

    float acc[4][4];
#pragma unroll
    for (int i = 0; i < 4; i++)
#pragma unroll
        for (int j = 0; j < 4; j++) acc[i][j] = 0.f;

#pragma unroll 1
    for (int cc = 0; cc < 8; cc++) {
        __syncthreads();
        {
            const int c = cc * 32 + scl;
            const int g = c >> 3;
            const size_t ga = (size_t)c * HW + wbase + sp1 * 8;
            const int pix = sp1 * 8;
            {
                float a = g_rstd[bb * 32 + g] * gq[c];
                float d = fmaf(-g_mean[bb * 32 + g], a, bq[c]);
                float4 v0 = *(const float4*)(qb + ga);
                float4 v1 = *(const float4*)(qb + ga + 4);
                uint4 t0, t1;
                t0.x = f2tf32(fmaf(v0.x, a, d)); t0.y = f2tf32(fmaf(v0.y, a, d));
                t0.z = f2tf32(fmaf(v0.z, a, d)); t0.w = f2tf32(fmaf(v0.w, a, d));
                t1.x = f2tf32(fmaf(v1.x, a, d)); t1.y = f2tf32(fmaf(v1.y, a, d));
                t1.z = f2tf32(fmaf(v1.z, a, d)); t1.w = f2tf32(fmaf(v1.w, a, d));
                *(uint4*)&sQ[scl * ST + pix]     = t0;
                *(uint4*)&sQ[scl * ST + pix + 4] = t1;
            }
            {
                float a = g_rstd[256 + bb * 32 + g] * gk[c];
                float d = fmaf(-g_mean[256 + bb * 32 + g], a, bk[c]);
                float4 v0 = *(const float4*)(kb + ga);
                float4 v1 = *(const float4*)(kb + ga + 4);
                uint4 t0, t1;
                t0.x = f2tf32(fmaf(v0.x, a, d)); t0.y = f2tf32(fmaf(v0.y, a, d));
                t0.z = f2tf32(fmaf(v0.z, a, d)); t0.w = f2tf32(fmaf(v0.w, a, d));
                t1.x = f2tf32(fmaf(v1.x, a, d)); t1.y = f2tf32(fmaf(v1.y, a, d));
                t1.z = f2tf32(fmaf(v1.z, a, d)); t1.w = f2tf32(fmaf(v1.w, a, d));
                *(uint4*)&sK[scl * ST + pix]     = t0;
                *(uint4*)&sK[scl * ST + pix + 4] = t1;
            }
        }
        __syncthreads();

#pragma unroll
        for (int ks = 0; ks < 4; ks++) {
            const int k0 = ks * 8 + (lane & 3);
            const int mrow = wm * 16 + (lane >> 2);
            uint32_t a[4];
            a[0] = sQ[k0 * ST + mrow];
            a[1] = sQ[k0 * ST + mrow + 8];
            a[2] = sQ[(k0 + 4) * ST + mrow];
            a[3] = sQ[(k0 + 4) * ST + mrow + 8];
#pragma unroll
            for (int nb = 0; nb < 4; nb++) {
                const int ncol = wn * 32 + nb * 8 + (lane >> 2);
                uint32_t b0 = sK[k0 * ST + ncol];
                uint32_t b1 = sK[(k0 + 4) * ST + ncol];
                mma1688(acc[nb], a, b0, b1);
            }
        }
    }
    __syncthreads();

    {
        const int r0 = wm * 16 + (lane >> 2);
        const int c0 = wn * 32 + (lane & 3) * 2;
#pragma unroll
        for (int nb = 0; nb < 4; nb++) {
            *(float2*)&sP[r0 * ST + c0 + nb * 8] =
                make_float2(acc[nb][0] * 0.0625f, acc[nb][1] * 0.0625f);
            *(float2*)&sP[(r0 + 8) * ST + c0 + nb * 8] =
                make_float2(acc[nb][2] * 0.0625f, acc[nb][3] * 0.0625f);
        }
    }
    __syncthreads();

    {
        const int row = tid >> 2;
        const int qq  = tid & 3;
        float v[16];
        *(float4*)&v[0]  = *(float4*)&sP[row * ST + qq * 16];
        *(float4*)&v[4]  = *(float4*)&sP[row * ST + qq * 16 + 4];
        *(float4*)&v[8]  = *(float4*)&sP[row * ST + qq * 16 + 8];
        *(float4*)&v[12] = *(float4*)&sP[row * ST + qq * 16 + 12];
        float mx = v[0];
#pragma unroll
        for (int i = 1; i < 16; i++) mx = fmaxf(mx, v[i]);
        mx = fmaxf(mx, __shfl_xor_sync(0xffffffffu, mx, 1));
        mx = fmaxf(mx, __shfl_xor_sync(0xffffffffu, mx, 2));
        float sum = 0.f;
#pragma unroll
        for (int i = 0; i < 16; i++) { v[i] = __expf(v[i] - mx); sum += v[i]; }
        sum += __shfl_xor_sync(0xffffffffu, sum, 1);
        sum += __shfl_xor_sync(0xffffffffu, sum, 2);
        float inv = 1.f / sum;
        uint32_t* sPu = (uint32_t*)sP;
#pragma unroll
        for (int i = 0; i < 16; i++)
            sPu[row * ST + qq * 16 + i] = f2tf32(v[i] * inv);
    }
    __syncthreads();

    const uint32_t* sPu = (const uint32_t*)sP;
    uint32_t* sO = sQ;

#pragma unroll 1
    for (int cc = 0; cc < 8; cc++) {
        if (cc) __syncthreads();
        {
            const int c = cc * 32 + scl;
            const int g = c >> 3;
            const size_t ga = (size_t)c * HW + wbase + sp1 * 8;
            const int pix = sp1 * 8;
            float a = g_rstd[256 + bb * 32 + g] * gk[c];
            float d = fmaf(-g_mean[256 + bb * 32 + g], a, bk[c]);
            float4 v0 = *(const float4*)(kb + ga);
            float4 v1 = *(const float4*)(kb + ga + 4);
            uint4 t0, t1;
            t0.x = f2tf32(fmaf(v0.x, a, d)); t0.y = f2tf32(fmaf(v0.y, a, d));
            t0.z = f2tf32(fmaf(v0.z, a, d)); t0.w = f2tf32(fmaf(v0.w, a, d));
            t1.x = f2tf32(fmaf(v1.x, a, d)); t1.y = f2tf32(fmaf(v1.y, a, d));
            t1.z = f2tf32(fmaf(v1.z, a, d)); t1.w = f2tf32(fmaf(v1.w, a, d));
            *(uint4*)&sK[scl * ST + pix]     = t0;
            *(uint4*)&sK[scl * ST + pix + 4] = t1;
        }
        __syncthreads();

        float acc2[2][4];
#pragma unroll
        for (int nb = 0; nb < 2; nb++)
#pragma unroll
            for (int r = 0; r < 4; r++) acc2[nb][r] = 0.f;

#pragma unroll
        for (int ks = 0; ks < 8; ks++) {
            const int k0 = ks * 8 + (lane & 3);
            const int mrow = wm * 16 + (lane >> 2);
            uint32_t a[4];
            a[0] = sPu[mrow * ST + k0];
            a[1] = sPu[(mrow + 8) * ST + k0];
            a[2] = sPu[mrow * ST + k0 + 4];
            a[3] = sPu[(mrow + 8) * ST + k0 + 4];
#pragma unroll
            for (int nb = 0; nb < 2; nb++) {
                const int nch = wn * 16 + nb * 8 + (lane >> 2);
                uint32_t b0 = sK[nch * ST + k0];
                uint32_t b1 = sK[nch * ST + k0 + 4];
                mma1688(acc2[nb], a, b0, b1);
            }
        }

        {
            const int px = wm * 16 + (lane >> 2);
#pragma unroll
            for (int nb = 0; nb < 2; nb++) {
                const int chl = wn * 16 + nb * 8 + (lane & 3) * 2;
                float* sOf = (float*)sO;
                sOf[chl * ST + px]           = acc2[nb][0];
                sOf[(chl + 1) * ST + px]     = acc2[nb][1];
                sOf[chl * ST + px + 8]       = acc2[nb][2];
                sOf[(chl + 1) * ST + px + 8] = acc2[nb][3];
            }
        }
        __syncthreads();

        const float* sOf = (const float*)sO;
#pragma unroll
        for (int i = 0; i < 2; i++) {
            int seg = i * 256 + tid;
            int c_l = seg >> 4;
            int r4  = seg & 15;
            int p1w = r4 >> 1;
            int h   = (r4 & 1) * 4;
            size_t ga = (size_t)bb * IMG + (size_t)(cc * 32 + c_l) * HW +
                        base_px + p1w * 128 + h;
            float4 o = *(const float4*)&sOf[c_l * ST + p1w * 8 + h];
            float4 x = *(const float4*)(xlo + ga);
            o.x += x.x; o.y += x.y; o.z += x.z; o.w += x.w;
            *(float4*)(outp + ga) = o;
        }
    }
}

// ---------------------------------------------------------------------------
// Launcher
// ---------------------------------------------------------------------------
extern "C" void kernel_launch(void* const* d_in, const int* in_sizes, int n_in,
                              void* d_out, int out_size)
{
    const float* x_low  = (const float*)d_in[0];
    const float* x_high = (const float*)d_in[1];
    const float* wq     = (const float*)d_in[2];
    const float* wk     = (const float*)d_in[3];
    const float* gq     = (const float*)d_in[4];
    const float* bq     = (const float*)d_in[5];
    const float* gk     = (const float*)d_in[6];
    const float* bk     = (const float*)d_in[7];
    float* outp = (float*)d_out;

    prep_afrag<<<512, 256>>>(wq, wk);

    cudaFuncSetAttribute(proj_mma,
                         cudaFuncAttributeMaxDynamicSharedMemorySize,
                         PR_SMEM_BYTES);
    proj_mma<<<dim3(2, 1024, 2), 256, PR_SMEM_BYTES>>>(x_low, x_high);

    stats_kernel<<<512, 256>>>();
    attn_mma<<<2048, 256>>>(x_low, outp, gq, bq, gk, bk);
}

// round 7
// speedup vs baseline: 3.0374x; 1.0240x over previous
#include <cuda_runtime.h>
#include <cuda_fp16.h>
#include <cstdint>

// ---------------------------------------------------------------------------
// Problem constants
// ---------------------------------------------------------------------------
#define BATCH   8
#define CH      256
#define HW      16384
#define IMG     (CH * HW)
#define GROUPS  32
#define GSZ     (CH / GROUPS)
#define NPIX    64
#define EPS     1e-5f

// g_qraw/g_kraw use WINDOW-TILED pixel layout within each channel:
//   px' = window_id * 64 + (y&7)*8 + (x&7),  window_id = (y>>3)*16 + (x>>3)
static __device__ float g_qraw[(size_t)BATCH * IMG];
static __device__ float g_kraw[(size_t)BATCH * IMG];
static __device__ float g_mean[2 * BATCH * GROUPS];
static __device__ float g_rstd[2 * BATCH * GROUPS];
static __device__ uint32_t g_afrag[131072];

// ---------------------------------------------------------------------------
// helpers
// ---------------------------------------------------------------------------
__device__ __forceinline__ uint32_t f2tf32(float f) {
    uint32_t r;
    asm("cvt.rna.tf32.f32 %0, %1;" : "=r"(r) : "f"(f));
    return r;
}
__device__ __forceinline__ uint32_t pack_h2(float x, float y) {
    __half2 h = __float22half2_rn(make_float2(x, y));
    return *(uint32_t*)&h;
}

__device__ __forceinline__ void mma1688(float d[4], const uint32_t a[4],
                                        uint32_t b0, uint32_t b1) {
    asm volatile(
        "mma.sync.aligned.m16n8k8.row.col.f32.tf32.tf32.f32 "
        "{%0,%1,%2,%3}, {%4,%5,%6,%7}, {%8,%9}, {%0,%1,%2,%3};"
        : "+f"(d[0]), "+f"(d[1]), "+f"(d[2]), "+f"(d[3])
        : "r"(a[0]), "r"(a[1]), "r"(a[2]), "r"(a[3]), "r"(b0), "r"(b1));
}

__device__ __forceinline__ void mmaf16(float d[4], const uint32_t a[4],
                                       uint32_t b0, uint32_t b1) {
    asm volatile(
        "mma.sync.aligned.m16n8k16.row.col.f32.f16.f16.f32 "
        "{%0,%1,%2,%3}, {%4,%5,%6,%7}, {%8,%9}, {%0,%1,%2,%3};"
        : "+f"(d[0]), "+f"(d[1]), "+f"(d[2]), "+f"(d[3])
        : "r"(a[0]), "r"(a[1]), "r"(a[2]), "r"(a[3]), "r"(b0), "r"(b1));
}

__device__ __forceinline__ uint32_t smem_u32(const void* p) {
    uint32_t a;
    asm("{ .reg .u64 t; cvta.to.shared.u64 t, %1; cvt.u32.u64 %0, t; }"
        : "=r"(a) : "l"(p));
    return a;
}

__device__ __forceinline__ void cpa16(uint32_t dst, const void* src) {
    asm volatile("cp.async.cg.shared.global [%0], [%1], 16;"
                 :: "r"(dst), "l"(src));
}
#define CPA_COMMIT() asm volatile("cp.async.commit_group;" ::: "memory")
#define CPA_WAIT(N)  asm volatile("cp.async.wait_group %0;" :: "n"(N) : "memory")

// ---------------------------------------------------------------------------
// Kernel 0: build fragment-ordered tf32 A operand
// ---------------------------------------------------------------------------
__global__ void __launch_bounds__(256) prep_afrag(
    const float* __restrict__ wq, const float* __restrict__ wk)
{
    int idx = blockIdx.x * 256 + threadIdx.x;
    int reg  = idx & 3;
    int lane = (idx >> 2) & 31;
    int ks   = (idx >> 7) & 3;
    int mbg  = (idx >> 9) & 7;
    int c    = (idx >> 12) & 7;
    int mt   = (idx >> 15) & 1;
    int t    = (idx >> 16) & 1;

    int m = mt * 128 + mbg * 16 + (reg & 1) * 8 + (lane >> 2);
    int k = c * 32 + ks * 8 + ((reg >> 1) & 1) * 4 + (lane & 3);
    const float* W = t ? wk : wq;
    g_afrag[idx] = f2tf32(W[m * CH + k]);
}

// ---------------------------------------------------------------------------
// Kernel 1: projection GEMM (unchanged from R6; window-tiled epilogue)
// ---------------------------------------------------------------------------
#define BS_STRIDE 132
#define PR_A(buf)  ((buf) * 4096)
#define PR_B(buf)  (8192 + (buf) * (32 * BS_STRIDE))
#define PR_SMEM_BYTES ((8192 + 2 * 32 * BS_STRIDE) * 4)

__global__ void __launch_bounds__(256, 2) proj_mma(
    const float* __restrict__ xlo, const float* __restrict__ xhi)
{
    extern __shared__ __align__(16) uint32_t smu[];
    const uint32_t sbase = smem_u32(smu);

    const int tid  = threadIdx.x;
    const int wid  = tid >> 5;
    const int lane = tid & 31;

    const int mt = blockIdx.x;
    const int tz = blockIdx.z;
    const float* X = tz ? xhi : xlo;
    float*       Y = tz ? g_kraw : g_qraw;

    const int bb = blockIdx.y >> 7;
    const int yrow = blockIdx.y & 127;
    const int p0 = yrow << 7;
    const int m0 = mt << 7;

    const float* Xb = X + (size_t)bb * IMG + p0;
    const uint32_t* Ag = g_afrag + (size_t)(tz * 2 + mt) * 32768;

    const int wm = wid >> 2;
    const int wn = wid & 3;

    float acc[4][4][4];
#pragma unroll
    for (int i = 0; i < 4; i++)
#pragma unroll
        for (int j = 0; j < 4; j++)
#pragma unroll
            for (int r = 0; r < 4; r++) acc[i][j][r] = 0.f;

#pragma unroll
    for (int i = 0; i < 4; i++) {
        int idx = i * 256 + tid;
        cpa16(sbase + (PR_A(0) + idx * 4) * 4, Ag + idx * 4);
        int k = idx >> 5, nq = idx & 31;
        cpa16(sbase + (PR_B(0) + k * BS_STRIDE + nq * 4) * 4,
              Xb + (size_t)k * HW + nq * 4);
    }
    CPA_COMMIT();

#pragma unroll 1
    for (int c = 0; c < 8; c++) {
        const int buf = c & 1;

        if (c < 7) {
            const int kc = (c + 1) << 5;
            const uint32_t* Agc = Ag + (c + 1) * 4096;
#pragma unroll
            for (int i = 0; i < 4; i++) {
                int idx = i * 256 + tid;
                cpa16(sbase + (PR_A(buf ^ 1) + idx * 4) * 4, Agc + idx * 4);
                int k = idx >> 5, nq = idx & 31;
                cpa16(sbase + (PR_B(buf ^ 1) + k * BS_STRIDE + nq * 4) * 4,
                      Xb + (size_t)(kc + k) * HW + nq * 4);
            }
            CPA_COMMIT();
            CPA_WAIT(1);
        } else {
            CPA_WAIT(0);
        }
        __syncthreads();

        const uint32_t* Ab = smu + PR_A(buf);
        const uint32_t* Bb = smu + PR_B(buf);

#pragma unroll
        for (int ks = 0; ks < 4; ks++) {
            uint32_t afr[4][4];
#pragma unroll
            for (int mb = 0; mb < 4; mb++) {
                int mbg = wm * 4 + mb;
                *(uint4*)afr[mb] = *(const uint4*)&Ab[((mbg * 4 + ks) << 7) + (lane << 2)];
            }
            uint32_t bfr[4][2];
            const int krow = ks * 8 + (lane & 3);
            const int ncol = wn * 32 + (lane >> 2);
#pragma unroll
            for (int nb = 0; nb < 4; nb++) {
                bfr[nb][0] = Bb[krow * BS_STRIDE + ncol + nb * 8];
                bfr[nb][1] = Bb[(krow + 4) * BS_STRIDE + ncol + nb * 8];
            }
#pragma unroll
            for (int mb = 0; mb < 4; mb++)
#pragma unroll
                for (int nb = 0; nb < 4; nb++)
                    mma1688(acc[mb][nb], afr[mb], bfr[nb][0], bfr[nb][1]);
        }
        __syncthreads();
    }

    const int base2 = (yrow >> 3) * 1024 + (yrow & 7) * 8;
    float* Yb = Y + (size_t)bb * IMG + base2;
    const int rl = lane >> 2;
    const int cl = (lane & 3) * 2;
#pragma unroll
    for (int mb = 0; mb < 4; mb++) {
        int mrow = m0 + wm * 64 + mb * 16 + rl;
#pragma unroll
        for (int nb = 0; nb < 4; nb++) {
            int noff = (wn * 4 + nb) * 64 + cl;
            float2 v0 = make_float2(acc[mb][nb][0], acc[mb][nb][1]);
            float2 v1 = make_float2(acc[mb][nb][2], acc[mb][nb][3]);
            *(float2*)(Yb + (size_t)mrow * HW + noff)       = v0;
            *(float2*)(Yb + (size_t)(mrow + 8) * HW + noff) = v1;
        }
    }
}

// ---------------------------------------------------------------------------
// Kernel 2: GroupNorm statistics (unchanged).
// ---------------------------------------------------------------------------
__global__ void __launch_bounds__(256) stats_kernel()
{
    const int id  = blockIdx.x;
    const int t   = id >> 8;
    const int b   = (id >> 5) & 7;
    const int g   = id & 31;
    const int tid = threadIdx.x;

    const float* src = (t ? g_kraw : g_qraw) + (size_t)b * IMG + (size_t)g * (GSZ * HW);
    const float4* p4 = (const float4*)src;

    float s = 0.f, sq = 0.f;
#pragma unroll 4
    for (int i = 0; i < 128; i++) {
        float4 v = p4[(size_t)i * 256 + tid];
        s  += v.x + v.y + v.z + v.w;
        sq += v.x * v.x + v.y * v.y + v.z * v.z + v.w * v.w;
    }

    __shared__ float rs[256], rq[256];
    rs[tid] = s; rq[tid] = sq;
    __syncthreads();
    for (int o = 128; o > 0; o >>= 1) {
        if (tid < o) { rs[tid] += rs[tid + o]; rq[tid] += rq[tid + o]; }
        __syncthreads();
    }
    if (tid == 0) {
        const float invN = 1.f / (float)(GSZ * HW);
        float m   = rs[0] * invN;
        float var = rq[0] * invN - m * m;
        g_mean[id] = m;
        g_rstd[id] = rsqrtf(var + EPS);
    }
}

// ---------------------------------------------------------------------------
// Kernel 3: windowed attention via fp16 mma m16n8k16.
//  smem:
//   smA  : phase S Q/K in half2 CHANNEL-PAIR layout [16 pairs][64 px] (stride 72)
//          sQp @0, sKp @1152 ; later reused as f32 sO [32ch][64px] (stride 68)
//   sP   : f32 S matrix [64][68]
//   sPh  : half2 P, PIXEL-PAIR layout [64 rows][32 pairs] (stride 36)
//   sKv  : half2 K for PV, PIXEL-PAIR layout [32 ch][32 pairs] (stride 36)
// ---------------------------------------------------------------------------
#define QP_ST 72
#define SP_ST 68
#define PH_ST 36
#define KV_ST 36

__global__ void __launch_bounds__(256) attn_mma(
    const float* __restrict__ xlo, float* __restrict__ outp,
    const float* __restrict__ gq, const float* __restrict__ bq,
    const float* __restrict__ gk, const float* __restrict__ bk)
{
    __shared__ uint32_t smA[2304];       // sQp[0..1151], sKp[1152..2303]; later sO
    __shared__ float    sP[64 * SP_ST];
    __shared__ uint32_t sPh[64 * PH_ST];
    __shared__ uint32_t sKv[32 * KV_ST];

    const int tid  = threadIdx.x;
    const int wid  = tid >> 5;
    const int lane = tid & 31;

    const int bb  = blockIdx.x >> 8;
    const int wnd = blockIdx.x & 255;
    const int base_px = ((wnd >> 4) << 3) * 128 + ((wnd & 15) << 3);  // std layout
    const int wbase = wnd * 64;                                       // tiled layout

    const float* qb = g_qraw + (size_t)bb * IMG;
    const float* kb = g_kraw + (size_t)bb * IMG;

    const int wm = wid & 3;
    const int wn = wid >> 2;

    // staging mapping (phase S): thread owns channel-pair p, 4 pixels
    const int p_  = tid >> 4;          // 0..15
    const int pg  = (tid & 15) * 4;    // pixel offset 0..60

    float acc[4][4];
#pragma unroll
    for (int i = 0; i < 4; i++)
#pragma unroll
        for (int j = 0; j < 4; j++) acc[i][j] = 0.f;

    // ================= Phase S =================
#pragma unroll 1
    for (int cc = 0; cc < 8; cc++) {
        __syncthreads();
        {
            const int c0 = cc * 32 + 2 * p_;
            const int g  = c0 >> 3;
            const size_t ga0 = (size_t)c0 * HW + wbase + pg;
            // q pair
            {
                float rq_ = g_rstd[bb * 32 + g], mq_ = g_mean[bb * 32 + g];
                float a0 = rq_ * gq[c0],     d0 = fmaf(-mq_, a0, bq[c0]);
                float a1 = rq_ * gq[c0 + 1], d1 = fmaf(-mq_, a1, bq[c0 + 1]);
                float4 u0 = *(const float4*)(qb + ga0);
                float4 u1 = *(const float4*)(qb + ga0 + HW);
                uint4 t;
                t.x = pack_h2(fmaf(u0.x, a0, d0), fmaf(u1.x, a1, d1));
                t.y = pack_h2(fmaf(u0.y, a0, d0), fmaf(u1.y, a1, d1));
                t.z = pack_h2(fmaf(u0.z, a0, d0), fmaf(u1.z, a1, d1));
                t.w = pack_h2(fmaf(u0.w, a0, d0), fmaf(u1.w, a1, d1));
                *(uint4*)&smA[p_ * QP_ST + pg] = t;
            }
            // k pair
            {
                float rk_ = g_rstd[256 + bb * 32 + g], mk_ = g_mean[256 + bb * 32 + g];
                float a0 = rk_ * gk[c0],     d0 = fmaf(-mk_, a0, bk[c0]);
                float a1 = rk_ * gk[c0 + 1], d1 = fmaf(-mk_, a1, bk[c0 + 1]);
                float4 u0 = *(const float4*)(kb + ga0);
                float4 u1 = *(const float4*)(kb + ga0 + HW);
                uint4 t;
                t.x = pack_h2(fmaf(u0.x, a0, d0), fmaf(u1.x, a1, d1));
                t.y = pack_h2(fmaf(u0.y, a0, d0), fmaf(u1.y, a1, d1));
                t.z = pack_h2(fmaf(u0.z, a0, d0), fmaf(u1.z, a1, d1));
                t.w = pack_h2(fmaf(u0.w, a0, d0), fmaf(u1.w, a1, d1));
                *(uint4*)&smA[1152 + p_ * QP_ST + pg] = t;
            }
        }
        __syncthreads();

        // mma: 32 channels = 2 x k16
#pragma unroll
        for (int ks = 0; ks < 2; ks++) {
            const int kp = ks * 8 + (lane & 3);
            const int mrow = wm * 16 + (lane >> 2);
            uint32_t a[4];
            a[0] = smA[kp * QP_ST + mrow];
            a[1] = smA[kp * QP_ST + mrow + 8];
            a[2] = smA[(kp + 4) * QP_ST + mrow];
            a[3] = smA[(kp + 4) * QP_ST + mrow + 8];
#pragma unroll
            for (int nb = 0; nb < 4; nb++) {
                const int ncol = wn * 32 + nb * 8 + (lane >> 2);
                uint32_t b0 = smA[1152 + kp * QP_ST + ncol];
                uint32_t b1 = smA[1152 + (kp + 4) * QP_ST + ncol];
                mmaf16(acc[nb], a, b0, b1);
            }
        }
    }
    __syncthreads();

    // write S (scaled) to sP
    {
        const int r0 = wm * 16 + (lane >> 2);
        const int c0 = wn * 32 + (lane & 3) * 2;
#pragma unroll
        for (int nb = 0; nb < 4; nb++) {
            *(float2*)&sP[r0 * SP_ST + c0 + nb * 8] =
                make_float2(acc[nb][0] * 0.0625f, acc[nb][1] * 0.0625f);
            *(float2*)&sP[(r0 + 8) * SP_ST + c0 + nb * 8] =
                make_float2(acc[nb][2] * 0.0625f, acc[nb][3] * 0.0625f);
        }
    }
    __syncthreads();

    // ================= softmax -> sPh (half2 pixel pairs) =================
    {
        const int row = tid >> 2;
        const int qq  = tid & 3;
        float v[16];
        *(float4*)&v[0]  = *(float4*)&sP[row * SP_ST + qq * 16];
        *(float4*)&v[4]  = *(float4*)&sP[row * SP_ST + qq * 16 + 4];
        *(float4*)&v[8]  = *(float4*)&sP[row * SP_ST + qq * 16 + 8];
        *(float4*)&v[12] = *(float4*)&sP[row * SP_ST + qq * 16 + 12];
        float mx = v[0];
#pragma unroll
        for (int i = 1; i < 16; i++) mx = fmaxf(mx, v[i]);
        mx = fmaxf(mx, __shfl_xor_sync(0xffffffffu, mx, 1));
        mx = fmaxf(mx, __shfl_xor_sync(0xffffffffu, mx, 2));
        float sum = 0.f;
#pragma unroll
        for (int i = 0; i < 16; i++) { v[i] = __expf(v[i] - mx); sum += v[i]; }
        sum += __shfl_xor_sync(0xffffffffu, sum, 1);
        sum += __shfl_xor_sync(0xffffffffu, sum, 2);
        float inv = 1.f / sum;
        uint4 t0, t1;
        t0.x = pack_h2(v[0] * inv,  v[1] * inv);
        t0.y = pack_h2(v[2] * inv,  v[3] * inv);
        t0.z = pack_h2(v[4] * inv,  v[5] * inv);
        t0.w = pack_h2(v[6] * inv,  v[7] * inv);
        t1.x = pack_h2(v[8] * inv,  v[9] * inv);
        t1.y = pack_h2(v[10] * inv, v[11] * inv);
        t1.z = pack_h2(v[12] * inv, v[13] * inv);
        t1.w = pack_h2(v[14] * inv, v[15] * inv);
        *(uint4*)&sPh[row * PH_ST + qq * 8]     = t0;
        *(uint4*)&sPh[row * PH_ST + qq * 8 + 4] = t1;
    }
    __syncthreads();

    // ================= Phase PV =================
    float* sO = (float*)smA;            // [32 ch][64 px] stride 68

    // staging mapping (PV): thread owns channel c, 8 pixels (4 pairs)
    const int vc  = tid >> 3;           // 0..31
    const int vp  = (tid & 7) * 8;      // pixel offset
    const int vpg = (tid & 7) * 4;      // pair offset

#pragma unroll 1
    for (int cc = 0; cc < 8; cc++) {
        if (cc) __syncthreads();
        {
            const int c = cc * 32 + vc;
            const int g = c >> 3;
            const size_t ga = (size_t)c * HW + wbase + vp;
            float a = g_rstd[256 + bb * 32 + g] * gk[c];
            float d = fmaf(-g_mean[256 + bb * 32 + g], a, bk[c]);
            float4 v0 = *(const float4*)(kb + ga);
            float4 v1 = *(const float4*)(kb + ga + 4);
            uint4 t;
            t.x = pack_h2(fmaf(v0.x, a, d), fmaf(v0.y, a, d));
            t.y = pack_h2(fmaf(v0.z, a, d), fmaf(v0.w, a, d));
            t.z = pack_h2(fmaf(v1.x, a, d), fmaf(v1.y, a, d));
            t.w = pack_h2(fmaf(v1.z, a, d), fmaf(v1.w, a, d));
            *(uint4*)&sKv[vc * KV_ST + vpg] = t;
        }
        __syncthreads();

        float acc2[2][4];
#pragma unroll
        for (int nb = 0; nb < 2; nb++)
#pragma unroll
            for (int r = 0; r < 4; r++) acc2[nb][r] = 0.f;

        // 64 pixels = 4 x k16
#pragma unroll
        for (int ks = 0; ks < 4; ks++) {
            const int jp = ks * 8 + (lane & 3);
            const int i0 = wm * 16 + (lane >> 2);
            uint32_t a[4];
            a[0] = sPh[i0 * PH_ST + jp];
            a[1] = sPh[(i0 + 8) * PH_ST + jp];
            a[2] = sPh[i0 * PH_ST + jp + 4];
            a[3] = sPh[(i0 + 8) * PH_ST + jp + 4];
#pragma unroll
            for (int nb = 0; nb < 2; nb++) {
                const int c = wn * 16 + nb * 8 + (lane >> 2);
                uint32_t b0 = sKv[c * KV_ST + jp];
                uint32_t b1 = sKv[c * KV_ST + jp + 4];
                mmaf16(acc2[nb], a, b0, b1);
            }
        }

        // stage out-chunk to sO [ch][px]
        {
            const int px = wm * 16 + (lane >> 2);
#pragma unroll
            for (int nb = 0; nb < 2; nb++) {
                const int chl = wn * 16 + nb * 8 + (lane & 3) * 2;
                sO[chl * SP_ST + px]           = acc2[nb][0];
                sO[(chl + 1) * SP_ST + px]     = acc2[nb][1];
                sO[chl * SP_ST + px + 8]       = acc2[nb][2];
                sO[(chl + 1) * SP_ST + px + 8] = acc2[nb][3];
            }
        }
        __syncthreads();

        // gmem write + residual
#pragma unroll
        for (int i = 0; i < 2; i++) {
            int seg = i * 256 + tid;
            int c_l = seg >> 4;
            int r4  = seg & 15;
            int p1w = r4 >> 1;
            int h   = (r4 & 1) * 4;
            size_t ga = (size_t)bb * IMG + (size_t)(cc * 32 + c_l) * HW +
                        base_px + p1w * 128 + h;
            float4 o = *(const float4*)&sO[c_l * SP_ST + p1w * 8 + h];
            float4 x = *(const float4*)(xlo + ga);
            o.x += x.x; o.y += x.y; o.z += x.z; o.w += x.w;
            *(float4*)(outp + ga) = o;
        }
    }
}

// ---------------------------------------------------------------------------
// Launcher
// ---------------------------------------------------------------------------
extern "C" void kernel_launch(void* const* d_in, const int* in_sizes, int n_in,
                              void* d_out, int out_size)
{
    const float* x_low  = (const float*)d_in[0];
    const float* x_high = (const float*)d_in[1];
    const float* wq     = (const float*)d_in[2];
    const float* wk     = (const float*)d_in[3];
    const float* gq     = (const float*)d_in[4];
    const float* bq     = (const float*)d_in[5];
    const float* gk     = (const float*)d_in[6];
    const float* bk     = (const float*)d_in[7];
    float* outp = (float*)d_out;

    prep_afrag<<<512, 256>>>(wq, wk);

    cudaFuncSetAttribute(proj_mma,
                         cudaFuncAttributeMaxDynamicSharedMemorySize,
                         PR_SMEM_BYTES);
    proj_mma<<<dim3(2, 1024, 2), 256, PR_SMEM_BYTES>>>(x_low, x_high);

    stats_kernel<<<512, 256>>>();
    attn_mma<<<2048, 256>>>(x_low, outp, gq, bq, gk, bk);
}

// round 8
// speedup vs baseline: 3.2768x; 1.0788x over previous
#include <cuda_runtime.h>
#include <cuda_fp16.h>
#include <cstdint>

// ---------------------------------------------------------------------------
// Problem constants
// ---------------------------------------------------------------------------
#define BATCH   8
#define CH      256
#define HW      16384
#define IMG     (CH * HW)
#define GROUPS  32
#define GSZ     (CH / GROUPS)
#define NPIX    64
#define EPS     1e-5f

// g_qraw/g_kraw use WINDOW-TILED pixel layout within each channel:
//   px' = window_id * 64 + (y&7)*8 + (x&7),  window_id = (y>>3)*16 + (x>>3)
static __device__ float g_qraw[(size_t)BATCH * IMG];
static __device__ float g_kraw[(size_t)BATCH * IMG];
static __device__ float g_mean[2 * BATCH * GROUPS];
static __device__ float g_rstd[2 * BATCH * GROUPS];
static __device__ uint32_t g_afrag[131072];

// ---------------------------------------------------------------------------
// helpers
// ---------------------------------------------------------------------------
__device__ __forceinline__ uint32_t f2tf32(float f) {
    uint32_t r;
    asm("cvt.rna.tf32.f32 %0, %1;" : "=r"(r) : "f"(f));
    return r;
}
__device__ __forceinline__ uint32_t pack_h2(float x, float y) {
    __half2 h = __float22half2_rn(make_float2(x, y));
    return *(uint32_t*)&h;
}

__device__ __forceinline__ void mma1688(float d[4], const uint32_t a[4],
                                        uint32_t b0, uint32_t b1) {
    asm volatile(
        "mma.sync.aligned.m16n8k8.row.col.f32.tf32.tf32.f32 "
        "{%0,%1,%2,%3}, {%4,%5,%6,%7}, {%8,%9}, {%0,%1,%2,%3};"
        : "+f"(d[0]), "+f"(d[1]), "+f"(d[2]), "+f"(d[3])
        : "r"(a[0]), "r"(a[1]), "r"(a[2]), "r"(a[3]), "r"(b0), "r"(b1));
}

__device__ __forceinline__ void mmaf16(float d[4], const uint32_t a[4],
                                       uint32_t b0, uint32_t b1) {
    asm volatile(
        "mma.sync.aligned.m16n8k16.row.col.f32.f16.f16.f32 "
        "{%0,%1,%2,%3}, {%4,%5,%6,%7}, {%8,%9}, {%0,%1,%2,%3};"
        : "+f"(d[0]), "+f"(d[1]), "+f"(d[2]), "+f"(d[3])
        : "r"(a[0]), "r"(a[1]), "r"(a[2]), "r"(a[3]), "r"(b0), "r"(b1));
}

__device__ __forceinline__ uint32_t smem_u32(const void* p) {
    uint32_t a;
    asm("{ .reg .u64 t; cvta.to.shared.u64 t, %1; cvt.u32.u64 %0, t; }"
        : "=r"(a) : "l"(p));
    return a;
}

__device__ __forceinline__ void cpa16(uint32_t dst, const void* src) {
    asm volatile("cp.async.cg.shared.global [%0], [%1], 16;"
                 :: "r"(dst), "l"(src));
}
#define CPA_COMMIT() asm volatile("cp.async.commit_group;" ::: "memory")
#define CPA_WAIT(N)  asm volatile("cp.async.wait_group %0;" :: "n"(N) : "memory")

// ---------------------------------------------------------------------------
// Kernel 0: build fragment-ordered tf32 A operand
// ---------------------------------------------------------------------------
__global__ void __launch_bounds__(256) prep_afrag(
    const float* __restrict__ wq, const float* __restrict__ wk)
{
    int idx = blockIdx.x * 256 + threadIdx.x;
    int reg  = idx & 3;
    int lane = (idx >> 2) & 31;
    int ks   = (idx >> 7) & 3;
    int mbg  = (idx >> 9) & 7;
    int c    = (idx >> 12) & 7;
    int mt   = (idx >> 15) & 1;
    int t    = (idx >> 16) & 1;

    int m = mt * 128 + mbg * 16 + (reg & 1) * 8 + (lane >> 2);
    int k = c * 32 + ks * 8 + ((reg >> 1) & 1) * 4 + (lane & 3);
    const float* W = t ? wk : wq;
    g_afrag[idx] = f2tf32(W[m * CH + k]);
}

// ---------------------------------------------------------------------------
// Kernel 1: projection GEMM (unchanged; window-tiled epilogue)
// ---------------------------------------------------------------------------
#define BS_STRIDE 132
#define PR_A(buf)  ((buf) * 4096)
#define PR_B(buf)  (8192 + (buf) * (32 * BS_STRIDE))
#define PR_SMEM_BYTES ((8192 + 2 * 32 * BS_STRIDE) * 4)

__global__ void __launch_bounds__(256, 2) proj_mma(
    const float* __restrict__ xlo, const float* __restrict__ xhi)
{
    extern __shared__ __align__(16) uint32_t smu[];
    const uint32_t sbase = smem_u32(smu);

    const int tid  = threadIdx.x;
    const int wid  = tid >> 5;
    const int lane = tid & 31;

    const int mt = blockIdx.x;
    const int tz = blockIdx.z;
    const float* X = tz ? xhi : xlo;
    float*       Y = tz ? g_kraw : g_qraw;

    const int bb = blockIdx.y >> 7;
    const int yrow = blockIdx.y & 127;
    const int p0 = yrow << 7;
    const int m0 = mt << 7;

    const float* Xb = X + (size_t)bb * IMG + p0;
    const uint32_t* Ag = g_afrag + (size_t)(tz * 2 + mt) * 32768;

    const int wm = wid >> 2;
    const int wn = wid & 3;

    float acc[4][4][4];
#pragma unroll
    for (int i = 0; i < 4; i++)
#pragma unroll
        for (int j = 0; j < 4; j++)
#pragma unroll
            for (int r = 0; r < 4; r++) acc[i][j][r] = 0.f;

#pragma unroll
    for (int i = 0; i < 4; i++) {
        int idx = i * 256 + tid;
        cpa16(sbase + (PR_A(0) + idx * 4) * 4, Ag + idx * 4);
        int k = idx >> 5, nq = idx & 31;
        cpa16(sbase + (PR_B(0) + k * BS_STRIDE + nq * 4) * 4,
              Xb + (size_t)k * HW + nq * 4);
    }
    CPA_COMMIT();

#pragma unroll 1
    for (int c = 0; c < 8; c++) {
        const int buf = c & 1;

        if (c < 7) {
            const int kc = (c + 1) << 5;
            const uint32_t* Agc = Ag + (c + 1) * 4096;
#pragma unroll
            for (int i = 0; i < 4; i++) {
                int idx = i * 256 + tid;
                cpa16(sbase + (PR_A(buf ^ 1) + idx * 4) * 4, Agc + idx * 4);
                int k = idx >> 5, nq = idx & 31;
                cpa16(sbase + (PR_B(buf ^ 1) + k * BS_STRIDE + nq * 4) * 4,
                      Xb + (size_t)(kc + k) * HW + nq * 4);
            }
            CPA_COMMIT();
            CPA_WAIT(1);
        } else {
            CPA_WAIT(0);
        }
        __syncthreads();

        const uint32_t* Ab = smu + PR_A(buf);
        const uint32_t* Bb = smu + PR_B(buf);

#pragma unroll
        for (int ks = 0; ks < 4; ks++) {
            uint32_t afr[4][4];
#pragma unroll
            for (int mb = 0; mb < 4; mb++) {
                int mbg = wm * 4 + mb;
                *(uint4*)afr[mb] = *(const uint4*)&Ab[((mbg * 4 + ks) << 7) + (lane << 2)];
            }
            uint32_t bfr[4][2];
            const int krow = ks * 8 + (lane & 3);
            const int ncol = wn * 32 + (lane >> 2);
#pragma unroll
            for (int nb = 0; nb < 4; nb++) {
                bfr[nb][0] = Bb[krow * BS_STRIDE + ncol + nb * 8];
                bfr[nb][1] = Bb[(krow + 4) * BS_STRIDE + ncol + nb * 8];
            }
#pragma unroll
            for (int mb = 0; mb < 4; mb++)
#pragma unroll
                for (int nb = 0; nb < 4; nb++)
                    mma1688(acc[mb][nb], afr[mb], bfr[nb][0], bfr[nb][1]);
        }
        __syncthreads();
    }

    const int base2 = (yrow >> 3) * 1024 + (yrow & 7) * 8;
    float* Yb = Y + (size_t)bb * IMG + base2;
    const int rl = lane >> 2;
    const int cl = (lane & 3) * 2;
#pragma unroll
    for (int mb = 0; mb < 4; mb++) {
        int mrow = m0 + wm * 64 + mb * 16 + rl;
#pragma unroll
        for (int nb = 0; nb < 4; nb++) {
            int noff = (wn * 4 + nb) * 64 + cl;
            float2 v0 = make_float2(acc[mb][nb][0], acc[mb][nb][1]);
            float2 v1 = make_float2(acc[mb][nb][2], acc[mb][nb][3]);
            *(float2*)(Yb + (size_t)mrow * HW + noff)       = v0;
            *(float2*)(Yb + (size_t)(mrow + 8) * HW + noff) = v1;
        }
    }
}

// ---------------------------------------------------------------------------
// Kernel 2: GroupNorm statistics (unchanged).
// ---------------------------------------------------------------------------
__global__ void __launch_bounds__(256) stats_kernel()
{
    const int id  = blockIdx.x;
    const int t   = id >> 8;
    const int b   = (id >> 5) & 7;
    const int g   = id & 31;
    const int tid = threadIdx.x;

    const float* src = (t ? g_kraw : g_qraw) + (size_t)b * IMG + (size_t)g * (GSZ * HW);
    const float4* p4 = (const float4*)src;

    float s = 0.f, sq = 0.f;
#pragma unroll 4
    for (int i = 0; i < 128; i++) {
        float4 v = p4[(size_t)i * 256 + tid];
        s  += v.x + v.y + v.z + v.w;
        sq += v.x * v.x + v.y * v.y + v.z * v.z + v.w * v.w;
    }

    __shared__ float rs[256], rq[256];
    rs[tid] = s; rq[tid] = sq;
    __syncthreads();
    for (int o = 128; o > 0; o >>= 1) {
        if (tid < o) { rs[tid] += rs[tid + o]; rq[tid] += rq[tid + o]; }
        __syncthreads();
    }
    if (tid == 0) {
        const float invN = 1.f / (float)(GSZ * HW);
        float m   = rs[0] * invN;
        float var = rq[0] * invN - m * m;
        g_mean[id] = m;
        g_rstd[id] = rsqrtf(var + EPS);
    }
}

// ---------------------------------------------------------------------------
// Kernel 3: windowed attention, fp16 mma, K-resident, register-softmax,
// register-prefetch pipeline.
// Dynamic smem layout (uint32 words):
//   sQp   @0      : 16x72   phase-S Q (channel-pair half2)
//   sKp   @1152   : 16x72   phase-S K (channel-pair half2)
//   (sQp+sKp reused as f32 sO [32][68] in PV)
//   sPh   @2304   : 64x36   P half2 (pixel pairs)
//   sKv   @4608   : 256x36  K half2 (pixel pairs), ALL channels, persistent
//   pmax  @13824  : 128 f32 (row, half)
//   psum  @13952  : 128 f32
// total 14080 words = 56320 bytes
// ---------------------------------------------------------------------------
#define QP_ST 72
#define SP_ST 68
#define PH_ST 36
#define KV_ST 36
#define AT_QP   0
#define AT_KP   1152
#define AT_PH   2304
#define AT_KV   4608
#define AT_PMAX 13824
#define AT_PSUM 13952
#define AT_SMEM_BYTES (14080 * 4)

__global__ void __launch_bounds__(256) attn_mma(
    const float* __restrict__ xlo, float* __restrict__ outp,
    const float* __restrict__ gq, const float* __restrict__ bq,
    const float* __restrict__ gk, const float* __restrict__ bk)
{
    extern __shared__ __align__(16) uint32_t sm[];
    uint32_t* sQp = sm + AT_QP;
    uint32_t* sKp = sm + AT_KP;
    uint32_t* sPh = sm + AT_PH;
    uint32_t* sKv = sm + AT_KV;
    float*    pmax = (float*)(sm + AT_PMAX);
    float*    psum = (float*)(sm + AT_PSUM);

    const int tid  = threadIdx.x;
    const int wid  = tid >> 5;
    const int lane = tid & 31;

    const int bb  = blockIdx.x >> 8;
    const int wnd = blockIdx.x & 255;
    const int base_px = ((wnd >> 4) << 3) * 128 + ((wnd & 15) << 3);  // std layout
    const int wbase = wnd * 64;                                       // tiled layout

    const float* qb = g_qraw + (size_t)bb * IMG;
    const float* kb = g_kraw + (size_t)bb * IMG;

    const int wm = wid & 3;
    const int wn = wid >> 2;

    // staging mapping (phase S): thread owns channel-pair p_, 4 pixels
    const int p_  = tid >> 4;          // 0..15
    const int pg  = (tid & 15) * 4;    // pixel offset 0..60

    float acc[4][4];
#pragma unroll
    for (int i = 0; i < 4; i++)
#pragma unroll
        for (int j = 0; j < 4; j++) acc[i][j] = 0.f;

    // preload chunk 0 raw q/k
    float4 q0, q1, k0, k1;
    {
        const size_t ga0 = (size_t)(2 * p_) * HW + wbase + pg;
        q0 = *(const float4*)(qb + ga0);
        q1 = *(const float4*)(qb + ga0 + HW);
        k0 = *(const float4*)(kb + ga0);
        k1 = *(const float4*)(kb + ga0 + HW);
    }

    // ================= Phase S =================
#pragma unroll 1
    for (int cc = 0; cc < 8; cc++) {
        // normalize + pack current chunk (register work, pre-barrier)
        const int c0 = cc * 32 + 2 * p_;
        const int g  = c0 >> 3;
        uint4 tq, tk;
        uint2 kv0, kv1;
        {
            float rq_ = g_rstd[bb * 32 + g], mq_ = g_mean[bb * 32 + g];
            float a0 = rq_ * gq[c0],     d0 = fmaf(-mq_, a0, bq[c0]);
            float a1 = rq_ * gq[c0 + 1], d1 = fmaf(-mq_, a1, bq[c0 + 1]);
            tq.x = pack_h2(fmaf(q0.x, a0, d0), fmaf(q1.x, a1, d1));
            tq.y = pack_h2(fmaf(q0.y, a0, d0), fmaf(q1.y, a1, d1));
            tq.z = pack_h2(fmaf(q0.z, a0, d0), fmaf(q1.z, a1, d1));
            tq.w = pack_h2(fmaf(q0.w, a0, d0), fmaf(q1.w, a1, d1));
        }
        {
            float rk_ = g_rstd[256 + bb * 32 + g], mk_ = g_mean[256 + bb * 32 + g];
            float a0 = rk_ * gk[c0],     d0 = fmaf(-mk_, a0, bk[c0]);
            float a1 = rk_ * gk[c0 + 1], d1 = fmaf(-mk_, a1, bk[c0 + 1]);
            float f00 = fmaf(k0.x, a0, d0), f01 = fmaf(k0.y, a0, d0);
            float f02 = fmaf(k0.z, a0, d0), f03 = fmaf(k0.w, a0, d0);
            float f10 = fmaf(k1.x, a1, d1), f11 = fmaf(k1.y, a1, d1);
            float f12 = fmaf(k1.z, a1, d1), f13 = fmaf(k1.w, a1, d1);
            tk.x = pack_h2(f00, f10);
            tk.y = pack_h2(f01, f11);
            tk.z = pack_h2(f02, f12);
            tk.w = pack_h2(f03, f13);
            // PV pixel-pair layout copies
            kv0 = make_uint2(pack_h2(f00, f01), pack_h2(f02, f03));
            kv1 = make_uint2(pack_h2(f10, f11), pack_h2(f12, f13));
        }

        // prefetch next chunk raw q/k (latency hidden by barrier+mma)
        if (cc < 7) {
            const size_t gan = (size_t)((cc + 1) * 32 + 2 * p_) * HW + wbase + pg;
            q0 = *(const float4*)(qb + gan);
            q1 = *(const float4*)(qb + gan + HW);
            k0 = *(const float4*)(kb + gan);
            k1 = *(const float4*)(kb + gan + HW);
        }

        if (cc) __syncthreads();   // previous chunk's mma done reading sQp/sKp

        *(uint4*)&sQp[p_ * QP_ST + pg] = tq;
        *(uint4*)&sKp[p_ * QP_ST + pg] = tk;
        *(uint2*)&sKv[(size_t)c0 * KV_ST + (pg >> 1)]       = kv0;
        *(uint2*)&sKv[(size_t)(c0 + 1) * KV_ST + (pg >> 1)] = kv1;
        __syncthreads();

        // mma: 32 channels = 2 x k16
#pragma unroll
        for (int ks = 0; ks < 2; ks++) {
            const int kp = ks * 8 + (lane & 3);
            const int mrow = wm * 16 + (lane >> 2);
            uint32_t a[4];
            a[0] = sQp[kp * QP_ST + mrow];
            a[1] = sQp[kp * QP_ST + mrow + 8];
            a[2] = sQp[(kp + 4) * QP_ST + mrow];
            a[3] = sQp[(kp + 4) * QP_ST + mrow + 8];
#pragma unroll
            for (int nb = 0; nb < 4; nb++) {
                const int ncol = wn * 32 + nb * 8 + (lane >> 2);
                uint32_t b0 = sKp[kp * QP_ST + ncol];
                uint32_t b1 = sKp[(kp + 4) * QP_ST + ncol];
                mmaf16(acc[nb], a, b0, b1);
            }
        }
    }

    // ================= register softmax =================
    // lane holds rows rA=wm*16+(lane>>2), rB=rA+8; 8 cols in half wn.
    const int rA = wm * 16 + (lane >> 2);
    const int rB = rA + 8;
    {
        // scale
#pragma unroll
        for (int nb = 0; nb < 4; nb++)
#pragma unroll
            for (int r = 0; r < 4; r++) acc[nb][r] *= 0.0625f;

        // stage 1: half-row max
        float mA = acc[0][0], mB = acc[0][2];
#pragma unroll
        for (int nb = 0; nb < 4; nb++) {
            mA = fmaxf(mA, fmaxf(acc[nb][0], acc[nb][1]));
            mB = fmaxf(mB, fmaxf(acc[nb][2], acc[nb][3]));
        }
        mA = fmaxf(mA, __shfl_xor_sync(0xffffffffu, mA, 1));
        mA = fmaxf(mA, __shfl_xor_sync(0xffffffffu, mA, 2));
        mB = fmaxf(mB, __shfl_xor_sync(0xffffffffu, mB, 1));
        mB = fmaxf(mB, __shfl_xor_sync(0xffffffffu, mB, 2));
        __syncthreads();   // sQp/sKp done (last mma) — also orders pmax reuse
        if ((lane & 3) == 0) {
            pmax[rA * 2 + wn] = mA;
            pmax[rB * 2 + wn] = mB;
        }
        __syncthreads();

        // stage 2: full max, exp, half-row sum
        float MA = fmaxf(pmax[rA * 2], pmax[rA * 2 + 1]);
        float MB = fmaxf(pmax[rB * 2], pmax[rB * 2 + 1]);
        float sA = 0.f, sB = 0.f;
#pragma unroll
        for (int nb = 0; nb < 4; nb++) {
            acc[nb][0] = __expf(acc[nb][0] - MA);
            acc[nb][1] = __expf(acc[nb][1] - MA);
            acc[nb][2] = __expf(acc[nb][2] - MB);
            acc[nb][3] = __expf(acc[nb][3] - MB);
            sA += acc[nb][0] + acc[nb][1];
            sB += acc[nb][2] + acc[nb][3];
        }
        sA += __shfl_xor_sync(0xffffffffu, sA, 1);
        sA += __shfl_xor_sync(0xffffffffu, sA, 2);
        sB += __shfl_xor_sync(0xffffffffu, sB, 1);
        sB += __shfl_xor_sync(0xffffffffu, sB, 2);
        if ((lane & 3) == 0) {
            psum[rA * 2 + wn] = sA;
            psum[rB * 2 + wn] = sB;
        }
        __syncthreads();

        // stage 3: normalize, pack pixel-pairs into sPh
        float invA = 1.f / (psum[rA * 2] + psum[rA * 2 + 1]);
        float invB = 1.f / (psum[rB * 2] + psum[rB * 2 + 1]);
#pragma unroll
        for (int nb = 0; nb < 4; nb++) {
            int pcol = wn * 16 + nb * 4 + (lane & 3);
            sPh[rA * PH_ST + pcol] = pack_h2(acc[nb][0] * invA, acc[nb][1] * invA);
            sPh[rB * PH_ST + pcol] = pack_h2(acc[nb][2] * invB, acc[nb][3] * invB);
        }
    }
    __syncthreads();

    // ================= Phase PV (no gmem K, no staging) =================
    float* sO = (float*)sm;            // reuse sQp+sKp: [32 ch][64 px] stride 68

    // residual prefetch mapping: thread owns 2 float4 per chunk
    const int xc0 = tid >> 4;              // seg0 channel-local 0..15
    const int xr0 = tid & 15;
    const int xc1 = 16 + xc0;
    float4 xA, xB;
    {
        size_t ga = (size_t)bb * IMG + base_px +
                    (size_t)(xr0 >> 1) * 128 + (xr0 & 1) * 4;
        xA = *(const float4*)(xlo + ga + (size_t)xc0 * HW);
        xB = *(const float4*)(xlo + ga + (size_t)xc1 * HW);
    }

#pragma unroll 1
    for (int cc = 0; cc < 8; cc++) {
        float acc2[2][4];
#pragma unroll
        for (int nb = 0; nb < 2; nb++)
#pragma unroll
            for (int r = 0; r < 4; r++) acc2[nb][r] = 0.f;

        // 64 pixels = 4 x k16 ; operands sPh + resident sKv
#pragma unroll
        for (int ks = 0; ks < 4; ks++) {
            const int jp = ks * 8 + (lane & 3);
            const int i0 = wm * 16 + (lane >> 2);
            uint32_t a[4];
            a[0] = sPh[i0 * PH_ST + jp];
            a[1] = sPh[(i0 + 8) * PH_ST + jp];
            a[2] = sPh[i0 * PH_ST + jp + 4];
            a[3] = sPh[(i0 + 8) * PH_ST + jp + 4];
#pragma unroll
            for (int nb = 0; nb < 2; nb++) {
                const int c = cc * 32 + wn * 16 + nb * 8 + (lane >> 2);
                uint32_t b0 = sKv[c * KV_ST + jp];
                uint32_t b1 = sKv[c * KV_ST + jp + 4];
                mmaf16(acc2[nb], a, b0, b1);
            }
        }

        __syncthreads();   // previous chunk's out-write finished reading sO

        {
            const int px = wm * 16 + (lane >> 2);
#pragma unroll
            for (int nb = 0; nb < 2; nb++) {
                const int chl = wn * 16 + nb * 8 + (lane & 3) * 2;
                sO[chl * SP_ST + px]           = acc2[nb][0];
                sO[(chl + 1) * SP_ST + px]     = acc2[nb][1];
                sO[chl * SP_ST + px + 8]       = acc2[nb][2];
                sO[(chl + 1) * SP_ST + px + 8] = acc2[nb][3];
            }
        }
        __syncthreads();

        // out write + residual (x regs hold chunk cc)
        {
            size_t gbase = (size_t)bb * IMG + base_px +
                           (size_t)(xr0 >> 1) * 128 + (xr0 & 1) * 4;
            int so_off = (xr0 >> 1) * 8 + (xr0 & 1) * 4;
            float4 o0 = *(const float4*)&sO[xc0 * SP_ST + so_off];
            float4 o1 = *(const float4*)&sO[xc1 * SP_ST + so_off];
            o0.x += xA.x; o0.y += xA.y; o0.z += xA.z; o0.w += xA.w;
            o1.x += xB.x; o1.y += xB.y; o1.z += xB.z; o1.w += xB.w;
            *(float4*)(outp + gbase + (size_t)(cc * 32 + xc0) * HW) = o0;
            *(float4*)(outp + gbase + (size_t)(cc * 32 + xc1) * HW) = o1;
            if (cc < 7) {   // prefetch residual for next chunk
                xA = *(const float4*)(xlo + gbase + (size_t)((cc + 1) * 32 + xc0) * HW);
                xB = *(const float4*)(xlo + gbase + (size_t)((cc + 1) * 32 + xc1) * HW);
            }
        }
    }
}

// ---------------------------------------------------------------------------
// Launcher
// ---------------------------------------------------------------------------
extern "C" void kernel_launch(void* const* d_in, const int* in_sizes, int n_in,
                              void* d_out, int out_size)
{
    const float* x_low  = (const float*)d_in[0];
    const float* x_high = (const float*)d_in[1];
    const float* wq     = (const float*)d_in[2];
    const float* wk     = (const float*)d_in[3];
    const float* gq     = (const float*)d_in[4];
    const float* bq     = (const float*)d_in[5];
    const float* gk     = (const float*)d_in[6];
    const float* bk     = (const float*)d_in[7];
    float* outp = (float*)d_out;

    prep_afrag<<<512, 256>>>(wq, wk);

    cudaFuncSetAttribute(proj_mma,
                         cudaFuncAttributeMaxDynamicSharedMemorySize,
                         PR_SMEM_BYTES);
    proj_mma<<<dim3(2, 1024, 2), 256, PR_SMEM_BYTES>>>(x_low, x_high);

    stats_kernel<<<512, 256>>>();

    cudaFuncSetAttribute(attn_mma,
                         cudaFuncAttributeMaxDynamicSharedMemorySize,
                         AT_SMEM_BYTES);
    attn_mma<<<2048, 256, AT_SMEM_BYTES>>>(x_low, outp, gq, bq, gk, bk);
}

// round 9
// speedup vs baseline: 3.6708x; 1.1202x over previous
#include <cuda_runtime.h>
#include <cuda_fp16.h>
#include <cstdint>

// ---------------------------------------------------------------------------
// Problem constants
// ---------------------------------------------------------------------------
#define BATCH   8
#define CH      256
#define HW      16384
#define IMG     (CH * HW)
#define GROUPS  32
#define GSZ     (CH / GROUPS)
#define NPIX    64
#define EPS     1e-5f

// g_qraw/g_kraw: fp16, WINDOW-TILED pixel layout within each channel:
//   px' = window_id * 64 + (y&7)*8 + (x&7),  window_id = (y>>3)*16 + (x>>3)
static __device__ __half g_qraw[(size_t)BATCH * IMG];
static __device__ __half g_kraw[(size_t)BATCH * IMG];
static __device__ float g_mean[2 * BATCH * GROUPS];
static __device__ float g_rstd[2 * BATCH * GROUPS];
static __device__ uint32_t g_afrag[131072];
// per-(tensor,batch,group) x per-pixel-tile partial (sum, sumsq)
static __device__ float g_psum[512 * 256];

// ---------------------------------------------------------------------------
// helpers
// ---------------------------------------------------------------------------
__device__ __forceinline__ uint32_t f2tf32(float f) {
    uint32_t r;
    asm("cvt.rna.tf32.f32 %0, %1;" : "=r"(r) : "f"(f));
    return r;
}
__device__ __forceinline__ uint32_t pack_h2(float x, float y) {
    __half2 h = __float22half2_rn(make_float2(x, y));
    return *(uint32_t*)&h;
}
__device__ __forceinline__ float4 h4_to_f4(uint2 v) {
    float2 a = __half22float2(*(__half2*)&v.x);
    float2 b = __half22float2(*(__half2*)&v.y);
    return make_float4(a.x, a.y, b.x, b.y);
}

__device__ __forceinline__ void mma1688(float d[4], const uint32_t a[4],
                                        uint32_t b0, uint32_t b1) {
    asm volatile(
        "mma.sync.aligned.m16n8k8.row.col.f32.tf32.tf32.f32 "
        "{%0,%1,%2,%3}, {%4,%5,%6,%7}, {%8,%9}, {%0,%1,%2,%3};"
        : "+f"(d[0]), "+f"(d[1]), "+f"(d[2]), "+f"(d[3])
        : "r"(a[0]), "r"(a[1]), "r"(a[2]), "r"(a[3]), "r"(b0), "r"(b1));
}

__device__ __forceinline__ void mmaf16(float d[4], const uint32_t a[4],
                                       uint32_t b0, uint32_t b1) {
    asm volatile(
        "mma.sync.aligned.m16n8k16.row.col.f32.f16.f16.f32 "
        "{%0,%1,%2,%3}, {%4,%5,%6,%7}, {%8,%9}, {%0,%1,%2,%3};"
        : "+f"(d[0]), "+f"(d[1]), "+f"(d[2]), "+f"(d[3])
        : "r"(a[0]), "r"(a[1]), "r"(a[2]), "r"(a[3]), "r"(b0), "r"(b1));
}

__device__ __forceinline__ uint32_t smem_u32(const void* p) {
    uint32_t a;
    asm("{ .reg .u64 t; cvta.to.shared.u64 t, %1; cvt.u32.u64 %0, t; }"
        : "=r"(a) : "l"(p));
    return a;
}

__device__ __forceinline__ void cpa16(uint32_t dst, const void* src) {
    asm volatile("cp.async.cg.shared.global [%0], [%1], 16;"
                 :: "r"(dst), "l"(src));
}
#define CPA_COMMIT() asm volatile("cp.async.commit_group;" ::: "memory")
#define CPA_WAIT(N)  asm volatile("cp.async.wait_group %0;" :: "n"(N) : "memory")

// ---------------------------------------------------------------------------
// Kernel 0: build fragment-ordered tf32 A operand
// ---------------------------------------------------------------------------
__global__ void __launch_bounds__(256) prep_afrag(
    const float* __restrict__ wq, const float* __restrict__ wk)
{
    int idx = blockIdx.x * 256 + threadIdx.x;
    int reg  = idx & 3;
    int lane = (idx >> 2) & 31;
    int ks   = (idx >> 7) & 3;
    int mbg  = (idx >> 9) & 7;
    int c    = (idx >> 12) & 7;
    int mt   = (idx >> 15) & 1;
    int t    = (idx >> 16) & 1;

    int m = mt * 128 + mbg * 16 + (reg & 1) * 8 + (lane >> 2);
    int k = c * 32 + ks * 8 + ((reg >> 1) & 1) * 4 + (lane & 3);
    const float* W = t ? wk : wq;
    g_afrag[idx] = f2tf32(W[m * CH + k]);
}

// ---------------------------------------------------------------------------
// Kernel 1: projection GEMM + fused GroupNorm partial stats.
// Output stored fp16, window-tiled.
// ---------------------------------------------------------------------------
#define BS_STRIDE 132
#define PR_A(buf)  ((buf) * 4096)
#define PR_B(buf)  (8192 + (buf) * (32 * BS_STRIDE))
#define PR_SMEM_BYTES ((8192 + 2 * 32 * BS_STRIDE) * 4)

__global__ void __launch_bounds__(256, 2) proj_mma(
    const float* __restrict__ xlo, const float* __restrict__ xhi)
{
    extern __shared__ __align__(16) uint32_t smu[];
    const uint32_t sbase = smem_u32(smu);

    const int tid  = threadIdx.x;
    const int wid  = tid >> 5;
    const int lane = tid & 31;

    const int mt = blockIdx.x;
    const int tz = blockIdx.z;
    const float* X = tz ? xhi : xlo;
    __half*      Y = tz ? g_kraw : g_qraw;

    const int bb = blockIdx.y >> 7;
    const int yrow = blockIdx.y & 127;
    const int p0 = yrow << 7;
    const int m0 = mt << 7;

    const float* Xb = X + (size_t)bb * IMG + p0;
    const uint32_t* Ag = g_afrag + (size_t)(tz * 2 + mt) * 32768;

    const int wm = wid >> 2;
    const int wn = wid & 3;

    float acc[4][4][4];
#pragma unroll
    for (int i = 0; i < 4; i++)
#pragma unroll
        for (int j = 0; j < 4; j++)
#pragma unroll
            for (int r = 0; r < 4; r++) acc[i][j][r] = 0.f;

#pragma unroll
    for (int i = 0; i < 4; i++) {
        int idx = i * 256 + tid;
        cpa16(sbase + (PR_A(0) + idx * 4) * 4, Ag + idx * 4);
        int k = idx >> 5, nq = idx & 31;
        cpa16(sbase + (PR_B(0) + k * BS_STRIDE + nq * 4) * 4,
              Xb + (size_t)k * HW + nq * 4);
    }
    CPA_COMMIT();

#pragma unroll 1
    for (int c = 0; c < 8; c++) {
        const int buf = c & 1;

        if (c < 7) {
            const int kc = (c + 1) << 5;
            const uint32_t* Agc = Ag + (c + 1) * 4096;
#pragma unroll
            for (int i = 0; i < 4; i++) {
                int idx = i * 256 + tid;
                cpa16(sbase + (PR_A(buf ^ 1) + idx * 4) * 4, Agc + idx * 4);
                int k = idx >> 5, nq = idx & 31;
                cpa16(sbase + (PR_B(buf ^ 1) + k * BS_STRIDE + nq * 4) * 4,
                      Xb + (size_t)(kc + k) * HW + nq * 4);
            }
            CPA_COMMIT();
            CPA_WAIT(1);
        } else {
            CPA_WAIT(0);
        }
        __syncthreads();

        const uint32_t* Ab = smu + PR_A(buf);
        const uint32_t* Bb = smu + PR_B(buf);

#pragma unroll
        for (int ks = 0; ks < 4; ks++) {
            uint32_t afr[4][4];
#pragma unroll
            for (int mb = 0; mb < 4; mb++) {
                int mbg = wm * 4 + mb;
                *(uint4*)afr[mb] = *(const uint4*)&Ab[((mbg * 4 + ks) << 7) + (lane << 2)];
            }
            uint32_t bfr[4][2];
            const int krow = ks * 8 + (lane & 3);
            const int ncol = wn * 32 + (lane >> 2);
#pragma unroll
            for (int nb = 0; nb < 4; nb++) {
                bfr[nb][0] = Bb[krow * BS_STRIDE + ncol + nb * 8];
                bfr[nb][1] = Bb[(krow + 4) * BS_STRIDE + ncol + nb * 8];
            }
#pragma unroll
            for (int mb = 0; mb < 4; mb++)
#pragma unroll
                for (int nb = 0; nb < 4; nb++)
                    mma1688(acc[mb][nb], afr[mb], bfr[nb][0], bfr[nb][1]);
        }
        __syncthreads();
    }

    // ---- fused GroupNorm partial statistics (deterministic trees) ----
    // rows wm*64+mb*16+{0..7}  -> group local gl = wm*8+mb*2
    // rows wm*64+mb*16+{8..15} -> gl+1
    __shared__ float red[16][4][2];
#pragma unroll
    for (int mb = 0; mb < 4; mb++) {
        float sE = 0.f, qE = 0.f, sO = 0.f, qO = 0.f;
#pragma unroll
        for (int nb = 0; nb < 4; nb++) {
            sE += acc[mb][nb][0] + acc[mb][nb][1];
            qE += acc[mb][nb][0] * acc[mb][nb][0] + acc[mb][nb][1] * acc[mb][nb][1];
            sO += acc[mb][nb][2] + acc[mb][nb][3];
            qO += acc[mb][nb][2] * acc[mb][nb][2] + acc[mb][nb][3] * acc[mb][nb][3];
        }
#pragma unroll
        for (int off = 16; off; off >>= 1) {
            sE += __shfl_xor_sync(0xffffffffu, sE, off);
            qE += __shfl_xor_sync(0xffffffffu, qE, off);
            sO += __shfl_xor_sync(0xffffffffu, sO, off);
            qO += __shfl_xor_sync(0xffffffffu, qO, off);
        }
        if (lane == 0) {
            int gl = wm * 8 + mb * 2;
            red[gl][wn][0] = sE;     red[gl][wn][1] = qE;
            red[gl + 1][wn][0] = sO; red[gl + 1][wn][1] = qO;
        }
    }
    __syncthreads();
    if (tid < 32) {
        int gl = tid >> 1, sq = tid & 1;
        float v = red[gl][0][sq] + red[gl][1][sq] + red[gl][2][sq] + red[gl][3][sq];
        g_psum[((size_t)((tz * 8 + bb) * 32) + mt * 16 + gl) * 256 + yrow * 2 + sq] = v;
    }

    // ---- epilogue: fp16 window-tiled store ----
    const int base2 = (yrow >> 3) * 1024 + (yrow & 7) * 8;
    __half* Yb = Y + (size_t)bb * IMG + base2;
    const int rl = lane >> 2;
    const int cl = (lane & 3) * 2;
#pragma unroll
    for (int mb = 0; mb < 4; mb++) {
        int mrow = m0 + wm * 64 + mb * 16 + rl;
#pragma unroll
        for (int nb = 0; nb < 4; nb++) {
            int noff = (wn * 4 + nb) * 64 + cl;
            __half2 v0 = __floats2half2_rn(acc[mb][nb][0], acc[mb][nb][1]);
            __half2 v1 = __floats2half2_rn(acc[mb][nb][2], acc[mb][nb][3]);
            *(__half2*)(Yb + (size_t)mrow * HW + noff)       = v0;
            *(__half2*)(Yb + (size_t)(mrow + 8) * HW + noff) = v1;
        }
    }
}

// ---------------------------------------------------------------------------
// Kernel 2: GroupNorm stats finalize (reduce 128 pixel-tile partials).
// ---------------------------------------------------------------------------
__global__ void __launch_bounds__(128) stats_finalize()
{
    const int id  = blockIdx.x;     // 0..511 = (t*8+b)*32+g
    const int tid = threadIdx.x;
    const float* p = g_psum + (size_t)id * 256;

    __shared__ float rs[128], rq[128];
    rs[tid] = p[tid * 2];
    rq[tid] = p[tid * 2 + 1];
    __syncthreads();
    for (int o = 64; o; o >>= 1) {
        if (tid < o) { rs[tid] += rs[tid + o]; rq[tid] += rq[tid + o]; }
        __syncthreads();
    }
    if (tid == 0) {
        const float invN = 1.f / (float)(GSZ * HW);
        float m   = rs[0] * invN;
        float var = rq[0] * invN - m * m;
        g_mean[id] = m;
        g_rstd[id] = rsqrtf(var + EPS);
    }
}

// ---------------------------------------------------------------------------
// Kernel 3: windowed attention (fp16 raw q/k reads; otherwise as R8).
// ---------------------------------------------------------------------------
#define QP_ST 72
#define SP_ST 68
#define PH_ST 36
#define KV_ST 36
#define AT_QP   0
#define AT_KP   1152
#define AT_PH   2304
#define AT_KV   4608
#define AT_PMAX 13824
#define AT_PSUM 13952
#define AT_SMEM_BYTES (14080 * 4)

__global__ void __launch_bounds__(256) attn_mma(
    const float* __restrict__ xlo, float* __restrict__ outp,
    const float* __restrict__ gq, const float* __restrict__ bq,
    const float* __restrict__ gk, const float* __restrict__ bk)
{
    extern __shared__ __align__(16) uint32_t sm[];
    uint32_t* sQp = sm + AT_QP;
    uint32_t* sKp = sm + AT_KP;
    uint32_t* sPh = sm + AT_PH;
    uint32_t* sKv = sm + AT_KV;
    float*    pmax = (float*)(sm + AT_PMAX);
    float*    psum = (float*)(sm + AT_PSUM);

    const int tid  = threadIdx.x;
    const int wid  = tid >> 5;
    const int lane = tid & 31;

    const int bb  = blockIdx.x >> 8;
    const int wnd = blockIdx.x & 255;
    const int base_px = ((wnd >> 4) << 3) * 128 + ((wnd & 15) << 3);
    const int wbase = wnd * 64;

    const __half* qb = g_qraw + (size_t)bb * IMG;
    const __half* kb = g_kraw + (size_t)bb * IMG;

    const int wm = wid & 3;
    const int wn = wid >> 2;

    const int p_  = tid >> 4;
    const int pg  = (tid & 15) * 4;

    float acc[4][4];
#pragma unroll
    for (int i = 0; i < 4; i++)
#pragma unroll
        for (int j = 0; j < 4; j++) acc[i][j] = 0.f;

    // preload chunk 0 raw q/k (fp16)
    uint2 q0h, q1h, k0h, k1h;
    {
        const size_t ga0 = (size_t)(2 * p_) * HW + wbase + pg;
        q0h = *(const uint2*)(qb + ga0);
        q1h = *(const uint2*)(qb + ga0 + HW);
        k0h = *(const uint2*)(kb + ga0);
        k1h = *(const uint2*)(kb + ga0 + HW);
    }

    // ================= Phase S =================
#pragma unroll 1
    for (int cc = 0; cc < 8; cc++) {
        const int c0 = cc * 32 + 2 * p_;
        const int g  = c0 >> 3;
        float4 q0 = h4_to_f4(q0h), q1 = h4_to_f4(q1h);
        float4 k0 = h4_to_f4(k0h), k1 = h4_to_f4(k1h);
        uint4 tq, tk;
        uint2 kv0, kv1;
        {
            float rq_ = g_rstd[bb * 32 + g], mq_ = g_mean[bb * 32 + g];
            float a0 = rq_ * gq[c0],     d0 = fmaf(-mq_, a0, bq[c0]);
            float a1 = rq_ * gq[c0 + 1], d1 = fmaf(-mq_, a1, bq[c0 + 1]);
            tq.x = pack_h2(fmaf(q0.x, a0, d0), fmaf(q1.x, a1, d1));
            tq.y = pack_h2(fmaf(q0.y, a0, d0), fmaf(q1.y, a1, d1));
            tq.z = pack_h2(fmaf(q0.z, a0, d0), fmaf(q1.z, a1, d1));
            tq.w = pack_h2(fmaf(q0.w, a0, d0), fmaf(q1.w, a1, d1));
        }
        {
            float rk_ = g_rstd[256 + bb * 32 + g], mk_ = g_mean[256 + bb * 32 + g];
            float a0 = rk_ * gk[c0],     d0 = fmaf(-mk_, a0, bk[c0]);
            float a1 = rk_ * gk[c0 + 1], d1 = fmaf(-mk_, a1, bk[c0 + 1]);
            float f00 = fmaf(k0.x, a0, d0), f01 = fmaf(k0.y, a0, d0);
            float f02 = fmaf(k0.z, a0, d0), f03 = fmaf(k0.w, a0, d0);
            float f10 = fmaf(k1.x, a1, d1), f11 = fmaf(k1.y, a1, d1);
            float f12 = fmaf(k1.z, a1, d1), f13 = fmaf(k1.w, a1, d1);
            tk.x = pack_h2(f00, f10);
            tk.y = pack_h2(f01, f11);
            tk.z = pack_h2(f02, f12);
            tk.w = pack_h2(f03, f13);
            kv0 = make_uint2(pack_h2(f00, f01), pack_h2(f02, f03));
            kv1 = make_uint2(pack_h2(f10, f11), pack_h2(f12, f13));
        }

        if (cc < 7) {
            const size_t gan = (size_t)((cc + 1) * 32 + 2 * p_) * HW + wbase + pg;
            q0h = *(const uint2*)(qb + gan);
            q1h = *(const uint2*)(qb + gan + HW);
            k0h = *(const uint2*)(kb + gan);
            k1h = *(const uint2*)(kb + gan + HW);
        }

        if (cc) __syncthreads();

        *(uint4*)&sQp[p_ * QP_ST + pg] = tq;
        *(uint4*)&sKp[p_ * QP_ST + pg] = tk;
        *(uint2*)&sKv[(size_t)c0 * KV_ST + (pg >> 1)]       = kv0;
        *(uint2*)&sKv[(size_t)(c0 + 1) * KV_ST + (pg >> 1)] = kv1;
        __syncthreads();

#pragma unroll
        for (int ks = 0; ks < 2; ks++) {
            const int kp = ks * 8 + (lane & 3);
            const int mrow = wm * 16 + (lane >> 2);
            uint32_t a[4];
            a[0] = sQp[kp * QP_ST + mrow];
            a[1] = sQp[kp * QP_ST + mrow + 8];
            a[2] = sQp[(kp + 4) * QP_ST + mrow];
            a[3] = sQp[(kp + 4) * QP_ST + mrow + 8];
#pragma unroll
            for (int nb = 0; nb < 4; nb++) {
                const int ncol = wn * 32 + nb * 8 + (lane >> 2);
                uint32_t b0 = sKp[kp * QP_ST + ncol];
                uint32_t b1 = sKp[(kp + 4) * QP_ST + ncol];
                mmaf16(acc[nb], a, b0, b1);
            }
        }
    }

    // ================= register softmax =================
    const int rA = wm * 16 + (lane >> 2);
    const int rB = rA + 8;
    {
#pragma unroll
        for (int nb = 0; nb < 4; nb++)
#pragma unroll
            for (int r = 0; r < 4; r++) acc[nb][r] *= 0.0625f;

        float mA = acc[0][0], mB = acc[0][2];
#pragma unroll
        for (int nb = 0; nb < 4; nb++) {
            mA = fmaxf(mA, fmaxf(acc[nb][0], acc[nb][1]));
            mB = fmaxf(mB, fmaxf(acc[nb][2], acc[nb][3]));
        }
        mA = fmaxf(mA, __shfl_xor_sync(0xffffffffu, mA, 1));
        mA = fmaxf(mA, __shfl_xor_sync(0xffffffffu, mA, 2));
        mB = fmaxf(mB, __shfl_xor_sync(0xffffffffu, mB, 1));
        mB = fmaxf(mB, __shfl_xor_sync(0xffffffffu, mB, 2));
        __syncthreads();
        if ((lane & 3) == 0) {
            pmax[rA * 2 + wn] = mA;
            pmax[rB * 2 + wn] = mB;
        }
        __syncthreads();

        float MA = fmaxf(pmax[rA * 2], pmax[rA * 2 + 1]);
        float MB = fmaxf(pmax[rB * 2], pmax[rB * 2 + 1]);
        float sA = 0.f, sB = 0.f;
#pragma unroll
        for (int nb = 0; nb < 4; nb++) {
            acc[nb][0] = __expf(acc[nb][0] - MA);
            acc[nb][1] = __expf(acc[nb][1] - MA);
            acc[nb][2] = __expf(acc[nb][2] - MB);
            acc[nb][3] = __expf(acc[nb][3] - MB);
            sA += acc[nb][0] + acc[nb][1];
            sB += acc[nb][2] + acc[nb][3];
        }
        sA += __shfl_xor_sync(0xffffffffu, sA, 1);
        sA += __shfl_xor_sync(0xffffffffu, sA, 2);
        sB += __shfl_xor_sync(0xffffffffu, sB, 1);
        sB += __shfl_xor_sync(0xffffffffu, sB, 2);
        if ((lane & 3) == 0) {
            psum[rA * 2 + wn] = sA;
            psum[rB * 2 + wn] = sB;
        }
        __syncthreads();

        float invA = 1.f / (psum[rA * 2] + psum[rA * 2 + 1]);
        float invB = 1.f / (psum[rB * 2] + psum[rB * 2 + 1]);
#pragma unroll
        for (int nb = 0; nb < 4; nb++) {
            int pcol = wn * 16 + nb * 4 + (lane & 3);
            sPh[rA * PH_ST + pcol] = pack_h2(acc[nb][0] * invA, acc[nb][1] * invA);
            sPh[rB * PH_ST + pcol] = pack_h2(acc[nb][2] * invB, acc[nb][3] * invB);
        }
    }
    __syncthreads();

    // ================= Phase PV =================
    float* sO = (float*)sm;

    const int xc0 = tid >> 4;
    const int xr0 = tid & 15;
    const int xc1 = 16 + xc0;
    float4 xA, xB;
    {
        size_t ga = (size_t)bb * IMG + base_px +
                    (size_t)(xr0 >> 1) * 128 + (xr0 & 1) * 4;
        xA = *(const float4*)(xlo + ga + (size_t)xc0 * HW);
        xB = *(const float4*)(xlo + ga + (size_t)xc1 * HW);
    }

#pragma unroll 1
    for (int cc = 0; cc < 8; cc++) {
        float acc2[2][4];
#pragma unroll
        for (int nb = 0; nb < 2; nb++)
#pragma unroll
            for (int r = 0; r < 4; r++) acc2[nb][r] = 0.f;

#pragma unroll
        for (int ks = 0; ks < 4; ks++) {
            const int jp = ks * 8 + (lane & 3);
            const int i0 = wm * 16 + (lane >> 2);
            uint32_t a[4];
            a[0] = sPh[i0 * PH_ST + jp];
            a[1] = sPh[(i0 + 8) * PH_ST + jp];
            a[2] = sPh[i0 * PH_ST + jp + 4];
            a[3] = sPh[(i0 + 8) * PH_ST + jp + 4];
#pragma unroll
            for (int nb = 0; nb < 2; nb++) {
                const int c = cc * 32 + wn * 16 + nb * 8 + (lane >> 2);
                uint32_t b0 = sKv[c * KV_ST + jp];
                uint32_t b1 = sKv[c * KV_ST + jp + 4];
                mmaf16(acc2[nb], a, b0, b1);
            }
        }

        __syncthreads();

        {
            const int px = wm * 16 + (lane >> 2);
#pragma unroll
            for (int nb = 0; nb < 2; nb++) {
                const int chl = wn * 16 + nb * 8 + (lane & 3) * 2;
                sO[chl * SP_ST + px]           = acc2[nb][0];
                sO[(chl + 1) * SP_ST + px]     = acc2[nb][1];
                sO[chl * SP_ST + px + 8]       = acc2[nb][2];
                sO[(chl + 1) * SP_ST + px + 8] = acc2[nb][3];
            }
        }
        __syncthreads();

        {
            size_t gbase = (size_t)bb * IMG + base_px +
                           (size_t)(xr0 >> 1) * 128 + (xr0 & 1) * 4;
            int so_off = (xr0 >> 1) * 8 + (xr0 & 1) * 4;
            float4 o0 = *(const float4*)&sO[xc0 * SP_ST + so_off];
            float4 o1 = *(const float4*)&sO[xc1 * SP_ST + so_off];
            o0.x += xA.x; o0.y += xA.y; o0.z += xA.z; o0.w += xA.w;
            o1.x += xB.x; o1.y += xB.y; o1.z += xB.z; o1.w += xB.w;
            *(float4*)(outp + gbase + (size_t)(cc * 32 + xc0) * HW) = o0;
            *(float4*)(outp + gbase + (size_t)(cc * 32 + xc1) * HW) = o1;
            if (cc < 7) {
                xA = *(const float4*)(xlo + gbase + (size_t)((cc + 1) * 32 + xc0) * HW);
                xB = *(const float4*)(xlo + gbase + (size_t)((cc + 1) * 32 + xc1) * HW);
            }
        }
    }
}

// ---------------------------------------------------------------------------
// Launcher
// ---------------------------------------------------------------------------
extern "C" void kernel_launch(void* const* d_in, const int* in_sizes, int n_in,
                              void* d_out, int out_size)
{
    const float* x_low  = (const float*)d_in[0];
    const float* x_high = (const float*)d_in[1];
    const float* wq     = (const float*)d_in[2];
    const float* wk     = (const float*)d_in[3];
    const float* gq     = (const float*)d_in[4];
    const float* bq     = (const float*)d_in[5];
    const float* gk     = (const float*)d_in[6];
    const float* bk     = (const float*)d_in[7];
    float* outp = (float*)d_out;

    prep_afrag<<<512, 256>>>(wq, wk);

    cudaFuncSetAttribute(proj_mma,
                         cudaFuncAttributeMaxDynamicSharedMemorySize,
                         PR_SMEM_BYTES);
    proj_mma<<<dim3(2, 1024, 2), 256, PR_SMEM_BYTES>>>(x_low, x_high);

    stats_finalize<<<512, 128>>>();

    cudaFuncSetAttribute(attn_mma,
                         cudaFuncAttributeMaxDynamicSharedMemorySize,
                         AT_SMEM_BYTES);
    attn_mma<<<2048, 256, AT_SMEM_BYTES>>>(x_low, outp, gq, bq, gk, bk);
}

// round 10
// speedup vs baseline: 4.0668x; 1.1079x over previous
#include <cuda_runtime.h>
#include <cuda_fp16.h>
#include <cstdint>

// ---------------------------------------------------------------------------
// Problem constants
// ---------------------------------------------------------------------------
#define BATCH   8
#define CH      256
#define HW      16384
#define IMG     (CH * HW)
#define GROUPS  32
#define GSZ     (CH / GROUPS)
#define NPIX    64
#define EPS     1e-5f

// g_qraw/g_kraw: fp16, WINDOW-TILED pixel layout within each channel:
//   px' = window_id * 64 + (y&7)*8 + (x&7),  window_id = (y>>3)*16 + (x>>3)
static __device__ __half g_qraw[(size_t)BATCH * IMG];
static __device__ __half g_kraw[(size_t)BATCH * IMG];
static __device__ float g_mean[2 * BATCH * GROUPS];
static __device__ float g_rstd[2 * BATCH * GROUPS];
// Pre-permuted fp16 A fragments (half2 k-pairs, m16n8k16 layout):
// [t(2)][mt(2)][chunk(8)][mbg(8)*ks(2)][lane(32)][reg(4)]
static __device__ uint32_t g_afragh[65536];
// per-(tensor,batch,group) x per-pixel-tile partial (sum, sumsq)
static __device__ float g_psum[512 * 256];

// ---------------------------------------------------------------------------
// helpers
// ---------------------------------------------------------------------------
__device__ __forceinline__ uint32_t pack_h2(float x, float y) {
    __half2 h = __float22half2_rn(make_float2(x, y));
    return *(uint32_t*)&h;
}
__device__ __forceinline__ float4 h4_to_f4(uint2 v) {
    float2 a = __half22float2(*(__half2*)&v.x);
    float2 b = __half22float2(*(__half2*)&v.y);
    return make_float4(a.x, a.y, b.x, b.y);
}

__device__ __forceinline__ void mmaf16(float d[4], const uint32_t a[4],
                                       uint32_t b0, uint32_t b1) {
    asm volatile(
        "mma.sync.aligned.m16n8k16.row.col.f32.f16.f16.f32 "
        "{%0,%1,%2,%3}, {%4,%5,%6,%7}, {%8,%9}, {%0,%1,%2,%3};"
        : "+f"(d[0]), "+f"(d[1]), "+f"(d[2]), "+f"(d[3])
        : "r"(a[0]), "r"(a[1]), "r"(a[2]), "r"(a[3]), "r"(b0), "r"(b1));
}

__device__ __forceinline__ uint32_t smem_u32(const void* p) {
    uint32_t a;
    asm("{ .reg .u64 t; cvta.to.shared.u64 t, %1; cvt.u32.u64 %0, t; }"
        : "=r"(a) : "l"(p));
    return a;
}

__device__ __forceinline__ void cpa16(uint32_t dst, const void* src) {
    asm volatile("cp.async.cg.shared.global [%0], [%1], 16;"
                 :: "r"(dst), "l"(src));
}
#define CPA_COMMIT() asm volatile("cp.async.commit_group;" ::: "memory")
#define CPA_WAIT(N)  asm volatile("cp.async.wait_group %0;" :: "n"(N) : "memory")

// ---------------------------------------------------------------------------
// Kernel 0: build fragment-ordered fp16 A operand (half2 k-pairs).
// offset within (t,mt): chunk*2048 + mbg*256 + ks*128 + lane*4 + reg
// ---------------------------------------------------------------------------
__global__ void __launch_bounds__(256) prep_afrag(
    const float* __restrict__ wq, const float* __restrict__ wk)
{
    int idx = blockIdx.x * 256 + threadIdx.x;   // 0..65535
    int reg   = idx & 3;
    int lane  = (idx >> 2) & 31;
    int ks    = (idx >> 7) & 1;
    int mbg   = (idx >> 8) & 7;
    int chunk = (idx >> 11) & 7;
    int mt    = (idx >> 14) & 1;
    int t     = (idx >> 15) & 1;

    int m  = mt * 128 + mbg * 16 + (reg & 1) * 8 + (lane >> 2);
    int kp = (lane & 3) + ((reg >> 1) & 1) * 4;
    int k  = chunk * 32 + ks * 16 + kp * 2;
    const float* W = t ? wk : wq;
    g_afragh[idx] = pack_h2(W[m * CH + k], W[m * CH + k + 1]);
}

// ---------------------------------------------------------------------------
// Kernel 1: projection GEMM via fp16 m16n8k16 + fused GroupNorm partials.
// A: fp16 fragments via cp.async (8 KB/chunk, double-buffered).
// B: X loaded fp32 via LDG (prefetched), packed to half2 k-pairs, STS
//    into [16 kp][128 n] stride-136 buffers (conflict-free fragment LDS).
// Output fp16, window-tiled. Fused deterministic GroupNorm partial stats.
// ---------------------------------------------------------------------------
#define BH_ST 136

__global__ void __launch_bounds__(256, 2) proj_mma(
    const float* __restrict__ xlo, const float* __restrict__ xhi)
{
    __shared__ uint32_t sA[4096];     // A0 @0, A1 @2048
    __shared__ uint32_t sB[4352];     // B0 @0, B1 @2176
    const uint32_t aBase = smem_u32(sA);

    const int tid  = threadIdx.x;
    const int wid  = tid >> 5;
    const int lane = tid & 31;

    const int mt = blockIdx.x;
    const int tz = blockIdx.z;
    const float* X = tz ? xhi : xlo;
    __half*      Y = tz ? g_kraw : g_qraw;

    const int bb = blockIdx.y >> 7;
    const int yrow = blockIdx.y & 127;
    const int p0 = yrow << 7;
    const int m0 = mt << 7;

    const float* Xb = X + (size_t)bb * IMG + p0;
    const uint32_t* Agh = g_afragh + (size_t)(tz * 2 + mt) * 16384;

    const int wm = wid >> 2;
    const int wn = wid & 3;

    // B staging mapping: thread owns k-pair row kp, 8 n values
    const int kp = tid >> 4;          // 0..15
    const int nq = (tid & 15) * 8;    // 0..120

    float acc[4][4][4];
#pragma unroll
    for (int i = 0; i < 4; i++)
#pragma unroll
        for (int j = 0; j < 4; j++)
#pragma unroll
            for (int r = 0; r < 4; r++) acc[i][j][r] = 0.f;

    float4 b00, b01, b10, b11;
    // ---- prologue: chunk 0 ----
    {
        const float* r0 = Xb + (size_t)(2 * kp) * HW + nq;
        b00 = *(const float4*)(r0);
        b01 = *(const float4*)(r0 + 4);
        b10 = *(const float4*)(r0 + HW);
        b11 = *(const float4*)(r0 + HW + 4);
    }
    {
        uint4 t0, t1;
        t0.x = pack_h2(b00.x, b10.x); t0.y = pack_h2(b00.y, b10.y);
        t0.z = pack_h2(b00.z, b10.z); t0.w = pack_h2(b00.w, b10.w);
        t1.x = pack_h2(b01.x, b11.x); t1.y = pack_h2(b01.y, b11.y);
        t1.z = pack_h2(b01.z, b11.z); t1.w = pack_h2(b01.w, b11.w);
        *(uint4*)&sB[kp * BH_ST + nq]     = t0;
        *(uint4*)&sB[kp * BH_ST + nq + 4] = t1;
    }
#pragma unroll
    for (int i = 0; i < 2; i++) {
        int idx = i * 256 + tid;
        cpa16(aBase + idx * 16, Agh + idx * 4);
    }
    CPA_COMMIT();

#pragma unroll 1
    for (int c = 0; c < 8; c++) {
        const int buf = c & 1;
        CPA_WAIT(0);
        __syncthreads();

        // prefetch B(c+1) raw fp32 (latency hidden by compute)
        if (c < 7) {
            const float* r0 = Xb + (size_t)((c + 1) * 32 + 2 * kp) * HW + nq;
            b00 = *(const float4*)(r0);
            b01 = *(const float4*)(r0 + 4);
            b10 = *(const float4*)(r0 + HW);
            b11 = *(const float4*)(r0 + HW + 4);
        }

        const uint32_t* Ab = sA + buf * 2048;
        const uint32_t* Bb = sB + buf * 2176;

#pragma unroll
        for (int ks = 0; ks < 2; ks++) {
            uint32_t afr[4][4];
#pragma unroll
            for (int mb = 0; mb < 4; mb++) {
                int mbg = wm * 4 + mb;
                *(uint4*)afr[mb] =
                    *(const uint4*)&Ab[(mbg * 2 + ks) * 128 + lane * 4];
            }
            const int krow = ks * 8 + (lane & 3);
            const int ncol = wn * 32 + (lane >> 2);
#pragma unroll
            for (int nb = 0; nb < 4; nb++) {
                uint32_t b0 = Bb[krow * BH_ST + ncol + nb * 8];
                uint32_t b1 = Bb[(krow + 4) * BH_ST + ncol + nb * 8];
#pragma unroll
                for (int mb = 0; mb < 4; mb++)
                    mmaf16(acc[mb][nb], afr[mb], b0, b1);
            }
        }

        // stage next chunk (writes go to the other buffer; safe after the
        // barrier at loop top guaranteed all warps finished reading it)
        if (c < 7) {
            const int nb_ = buf ^ 1;
            uint4 t0, t1;
            t0.x = pack_h2(b00.x, b10.x); t0.y = pack_h2(b00.y, b10.y);
            t0.z = pack_h2(b00.z, b10.z); t0.w = pack_h2(b00.w, b10.w);
            t1.x = pack_h2(b01.x, b11.x); t1.y = pack_h2(b01.y, b11.y);
            t1.z = pack_h2(b01.z, b11.z); t1.w = pack_h2(b01.w, b11.w);
            *(uint4*)&sB[nb_ * 2176 + kp * BH_ST + nq]     = t0;
            *(uint4*)&sB[nb_ * 2176 + kp * BH_ST + nq + 4] = t1;
#pragma unroll
            for (int i = 0; i < 2; i++) {
                int idx = i * 256 + tid;
                cpa16(aBase + (nb_ * 2048 + idx * 4) * 4,
                      Agh + (c + 1) * 2048 + idx * 4);
            }
            CPA_COMMIT();
        }
    }

    // ---- fused GroupNorm partial statistics (deterministic trees) ----
    __shared__ float red[16][4][2];
#pragma unroll
    for (int mb = 0; mb < 4; mb++) {
        float sE = 0.f, qE = 0.f, sO = 0.f, qO = 0.f;
#pragma unroll
        for (int nb = 0; nb < 4; nb++) {
            sE += acc[mb][nb][0] + acc[mb][nb][1];
            qE += acc[mb][nb][0] * acc[mb][nb][0] + acc[mb][nb][1] * acc[mb][nb][1];
            sO += acc[mb][nb][2] + acc[mb][nb][3];
            qO += acc[mb][nb][2] * acc[mb][nb][2] + acc[mb][nb][3] * acc[mb][nb][3];
        }
#pragma unroll
        for (int off = 16; off; off >>= 1) {
            sE += __shfl_xor_sync(0xffffffffu, sE, off);
            qE += __shfl_xor_sync(0xffffffffu, qE, off);
            sO += __shfl_xor_sync(0xffffffffu, sO, off);
            qO += __shfl_xor_sync(0xffffffffu, qO, off);
        }
        if (lane == 0) {
            int gl = wm * 8 + mb * 2;
            red[gl][wn][0] = sE;     red[gl][wn][1] = qE;
            red[gl + 1][wn][0] = sO; red[gl + 1][wn][1] = qO;
        }
    }
    __syncthreads();
    if (tid < 32) {
        int gl = tid >> 1, sq = tid & 1;
        float v = red[gl][0][sq] + red[gl][1][sq] + red[gl][2][sq] + red[gl][3][sq];
        g_psum[((size_t)((tz * 8 + bb) * 32) + mt * 16 + gl) * 256 + yrow * 2 + sq] = v;
    }

    // ---- epilogue: fp16 window-tiled store ----
    const int base2 = (yrow >> 3) * 1024 + (yrow & 7) * 8;
    __half* Yb = Y + (size_t)bb * IMG + base2;
    const int rl = lane >> 2;
    const int cl = (lane & 3) * 2;
#pragma unroll
    for (int mb = 0; mb < 4; mb++) {
        int mrow = m0 + wm * 64 + mb * 16 + rl;
#pragma unroll
        for (int nb = 0; nb < 4; nb++) {
            int noff = (wn * 4 + nb) * 64 + cl;
            __half2 v0 = __floats2half2_rn(acc[mb][nb][0], acc[mb][nb][1]);
            __half2 v1 = __floats2half2_rn(acc[mb][nb][2], acc[mb][nb][3]);
            *(__half2*)(Yb + (size_t)mrow * HW + noff)       = v0;
            *(__half2*)(Yb + (size_t)(mrow + 8) * HW + noff) = v1;
        }
    }
}

// ---------------------------------------------------------------------------
// Kernel 2: GroupNorm stats finalize (reduce 128 pixel-tile partials).
// ---------------------------------------------------------------------------
__global__ void __launch_bounds__(128) stats_finalize()
{
    const int id  = blockIdx.x;
    const int tid = threadIdx.x;
    const float* p = g_psum + (size_t)id * 256;

    __shared__ float rs[128], rq[128];
    rs[tid] = p[tid * 2];
    rq[tid] = p[tid * 2 + 1];
    __syncthreads();
    for (int o = 64; o; o >>= 1) {
        if (tid < o) { rs[tid] += rs[tid + o]; rq[tid] += rq[tid + o]; }
        __syncthreads();
    }
    if (tid == 0) {
        const float invN = 1.f / (float)(GSZ * HW);
        float m   = rs[0] * invN;
        float var = rq[0] * invN - m * m;
        g_mean[id] = m;
        g_rstd[id] = rsqrtf(var + EPS);
    }
}

// ---------------------------------------------------------------------------
// Kernel 3: windowed attention (unchanged from R9).
// ---------------------------------------------------------------------------
#define QP_ST 72
#define SP_ST 68
#define PH_ST 36
#define KV_ST 36
#define AT_QP   0
#define AT_KP   1152
#define AT_PH   2304
#define AT_KV   4608
#define AT_PMAX 13824
#define AT_PSUM 13952
#define AT_SMEM_BYTES (14080 * 4)

__global__ void __launch_bounds__(256) attn_mma(
    const float* __restrict__ xlo, float* __restrict__ outp,
    const float* __restrict__ gq, const float* __restrict__ bq,
    const float* __restrict__ gk, const float* __restrict__ bk)
{
    extern __shared__ __align__(16) uint32_t sm[];
    uint32_t* sQp = sm + AT_QP;
    uint32_t* sKp = sm + AT_KP;
    uint32_t* sPh = sm + AT_PH;
    uint32_t* sKv = sm + AT_KV;
    float*    pmax = (float*)(sm + AT_PMAX);
    float*    psum = (float*)(sm + AT_PSUM);

    const int tid  = threadIdx.x;
    const int wid  = tid >> 5;
    const int lane = tid & 31;

    const int bb  = blockIdx.x >> 8;
    const int wnd = blockIdx.x & 255;
    const int base_px = ((wnd >> 4) << 3) * 128 + ((wnd & 15) << 3);
    const int wbase = wnd * 64;

    const __half* qb = g_qraw + (size_t)bb * IMG;
    const __half* kb = g_kraw + (size_t)bb * IMG;

    const int wm = wid & 3;
    const int wn = wid >> 2;

    const int p_  = tid >> 4;
    const int pg  = (tid & 15) * 4;

    float acc[4][4];
#pragma unroll
    for (int i = 0; i < 4; i++)
#pragma unroll
        for (int j = 0; j < 4; j++) acc[i][j] = 0.f;

    uint2 q0h, q1h, k0h, k1h;
    {
        const size_t ga0 = (size_t)(2 * p_) * HW + wbase + pg;
        q0h = *(const uint2*)(qb + ga0);
        q1h = *(const uint2*)(qb + ga0 + HW);
        k0h = *(const uint2*)(kb + ga0);
        k1h = *(const uint2*)(kb + ga0 + HW);
    }

    // ================= Phase S =================
#pragma unroll 1
    for (int cc = 0; cc < 8; cc++) {
        const int c0 = cc * 32 + 2 * p_;
        const int g  = c0 >> 3;
        float4 q0 = h4_to_f4(q0h), q1 = h4_to_f4(q1h);
        float4 k0 = h4_to_f4(k0h), k1 = h4_to_f4(k1h);
        uint4 tq, tk;
        uint2 kv0, kv1;
        {
            float rq_ = g_rstd[bb * 32 + g], mq_ = g_mean[bb * 32 + g];
            float a0 = rq_ * gq[c0],     d0 = fmaf(-mq_, a0, bq[c0]);
            float a1 = rq_ * gq[c0 + 1], d1 = fmaf(-mq_, a1, bq[c0 + 1]);
            tq.x = pack_h2(fmaf(q0.x, a0, d0), fmaf(q1.x, a1, d1));
            tq.y = pack_h2(fmaf(q0.y, a0, d0), fmaf(q1.y, a1, d1));
            tq.z = pack_h2(fmaf(q0.z, a0, d0), fmaf(q1.z, a1, d1));
            tq.w = pack_h2(fmaf(q0.w, a0, d0), fmaf(q1.w, a1, d1));
        }
        {
            float rk_ = g_rstd[256 + bb * 32 + g], mk_ = g_mean[256 + bb * 32 + g];
            float a0 = rk_ * gk[c0],     d0 = fmaf(-mk_, a0, bk[c0]);
            float a1 = rk_ * gk[c0 + 1], d1 = fmaf(-mk_, a1, bk[c0 + 1]);
            float f00 = fmaf(k0.x, a0, d0), f01 = fmaf(k0.y, a0, d0);
            float f02 = fmaf(k0.z, a0, d0), f03 = fmaf(k0.w, a0, d0);
            float f10 = fmaf(k1.x, a1, d1), f11 = fmaf(k1.y, a1, d1);
            float f12 = fmaf(k1.z, a1, d1), f13 = fmaf(k1.w, a1, d1);
            tk.x = pack_h2(f00, f10);
            tk.y = pack_h2(f01, f11);
            tk.z = pack_h2(f02, f12);
            tk.w = pack_h2(f03, f13);
            kv0 = make_uint2(pack_h2(f00, f01), pack_h2(f02, f03));
            kv1 = make_uint2(pack_h2(f10, f11), pack_h2(f12, f13));
        }

        if (cc < 7) {
            const size_t gan = (size_t)((cc + 1) * 32 + 2 * p_) * HW + wbase + pg;
            q0h = *(const uint2*)(qb + gan);
            q1h = *(const uint2*)(qb + gan + HW);
            k0h = *(const uint2*)(kb + gan);
            k1h = *(const uint2*)(kb + gan + HW);
        }

        if (cc) __syncthreads();

        *(uint4*)&sQp[p_ * QP_ST + pg] = tq;
        *(uint4*)&sKp[p_ * QP_ST + pg] = tk;
        *(uint2*)&sKv[(size_t)c0 * KV_ST + (pg >> 1)]       = kv0;
        *(uint2*)&sKv[(size_t)(c0 + 1) * KV_ST + (pg >> 1)] = kv1;
        __syncthreads();

#pragma unroll
        for (int ks = 0; ks < 2; ks++) {
            const int kp = ks * 8 + (lane & 3);
            const int mrow = wm * 16 + (lane >> 2);
            uint32_t a[4];
            a[0] = sQp[kp * QP_ST + mrow];
            a[1] = sQp[kp * QP_ST + mrow + 8];
            a[2] = sQp[(kp + 4) * QP_ST + mrow];
            a[3] = sQp[(kp + 4) * QP_ST + mrow + 8];
#pragma unroll
            for (int nb = 0; nb < 4; nb++) {
                const int ncol = wn * 32 + nb * 8 + (lane >> 2);
                uint32_t b0 = sKp[kp * QP_ST + ncol];
                uint32_t b1 = sKp[(kp + 4) * QP_ST + ncol];
                mmaf16(acc[nb], a, b0, b1);
            }
        }
    }

    // ================= register softmax =================
    const int rA = wm * 16 + (lane >> 2);
    const int rB = rA + 8;
    {
#pragma unroll
        for (int nb = 0; nb < 4; nb++)
#pragma unroll
            for (int r = 0; r < 4; r++) acc[nb][r] *= 0.0625f;

        float mA = acc[0][0], mB = acc[0][2];
#pragma unroll
        for (int nb = 0; nb < 4; nb++) {
            mA = fmaxf(mA, fmaxf(acc[nb][0], acc[nb][1]));
            mB = fmaxf(mB, fmaxf(acc[nb][2], acc[nb][3]));
        }
        mA = fmaxf(mA, __shfl_xor_sync(0xffffffffu, mA, 1));
        mA = fmaxf(mA, __shfl_xor_sync(0xffffffffu, mA, 2));
        mB = fmaxf(mB, __shfl_xor_sync(0xffffffffu, mB, 1));
        mB = fmaxf(mB, __shfl_xor_sync(0xffffffffu, mB, 2));
        __syncthreads();
        if ((lane & 3) == 0) {
            pmax[rA * 2 + wn] = mA;
            pmax[rB * 2 + wn] = mB;
        }
        __syncthreads();

        float MA = fmaxf(pmax[rA * 2], pmax[rA * 2 + 1]);
        float MB = fmaxf(pmax[rB * 2], pmax[rB * 2 + 1]);
        float sA = 0.f, sB = 0.f;
#pragma unroll
        for (int nb = 0; nb < 4; nb++) {
            acc[nb][0] = __expf(acc[nb][0] - MA);
            acc[nb][1] = __expf(acc[nb][1] - MA);
            acc[nb][2] = __expf(acc[nb][2] - MB);
            acc[nb][3] = __expf(acc[nb][3] - MB);
            sA += acc[nb][0] + acc[nb][1];
            sB += acc[nb][2] + acc[nb][3];
        }
        sA += __shfl_xor_sync(0xffffffffu, sA, 1);
        sA += __shfl_xor_sync(0xffffffffu, sA, 2);
        sB += __shfl_xor_sync(0xffffffffu, sB, 1);
        sB += __shfl_xor_sync(0xffffffffu, sB, 2);
        if ((lane & 3) == 0) {
            psum[rA * 2 + wn] = sA;
            psum[rB * 2 + wn] = sB;
        }
        __syncthreads();

        float invA = 1.f / (psum[rA * 2] + psum[rA * 2 + 1]);
        float invB = 1.f / (psum[rB * 2] + psum[rB * 2 + 1]);
#pragma unroll
        for (int nb = 0; nb < 4; nb++) {
            int pcol = wn * 16 + nb * 4 + (lane & 3);
            sPh[rA * PH_ST + pcol] = pack_h2(acc[nb][0] * invA, acc[nb][1] * invA);
            sPh[rB * PH_ST + pcol] = pack_h2(acc[nb][2] * invB, acc[nb][3] * invB);
        }
    }
    __syncthreads();

    // ================= Phase PV =================
    float* sO = (float*)sm;

    const int xc0 = tid >> 4;
    const int xr0 = tid & 15;
    const int xc1 = 16 + xc0;
    float4 xA, xB;
    {
        size_t ga = (size_t)bb * IMG + base_px +
                    (size_t)(xr0 >> 1) * 128 + (xr0 & 1) * 4;
        xA = *(const float4*)(xlo + ga + (size_t)xc0 * HW);
        xB = *(const float4*)(xlo + ga + (size_t)xc1 * HW);
    }

#pragma unroll 1
    for (int cc = 0; cc < 8; cc++) {
        float acc2[2][4];
#pragma unroll
        for (int nb = 0; nb < 2; nb++)
#pragma unroll
            for (int r = 0; r < 4; r++) acc2[nb][r] = 0.f;

#pragma unroll
        for (int ks = 0; ks < 4; ks++) {
            const int jp = ks * 8 + (lane & 3);
            const int i0 = wm * 16 + (lane >> 2);
            uint32_t a[4];
            a[0] = sPh[i0 * PH_ST + jp];
            a[1] = sPh[(i0 + 8) * PH_ST + jp];
            a[2] = sPh[i0 * PH_ST + jp + 4];
            a[3] = sPh[(i0 + 8) * PH_ST + jp + 4];
#pragma unroll
            for (int nb = 0; nb < 2; nb++) {
                const int c = cc * 32 + wn * 16 + nb * 8 + (lane >> 2);
                uint32_t b0 = sKv[c * KV_ST + jp];
                uint32_t b1 = sKv[c * KV_ST + jp + 4];
                mmaf16(acc2[nb], a, b0, b1);
            }
        }

        __syncthreads();

        {
            const int px = wm * 16 + (lane >> 2);
#pragma unroll
            for (int nb = 0; nb < 2; nb++) {
                const int chl = wn * 16 + nb * 8 + (lane & 3) * 2;
                sO[chl * SP_ST + px]           = acc2[nb][0];
                sO[(chl + 1) * SP_ST + px]     = acc2[nb][1];
                sO[chl * SP_ST + px + 8]       = acc2[nb][2];
                sO[(chl + 1) * SP_ST + px + 8] = acc2[nb][3];
            }
        }
        __syncthreads();

        {
            size_t gbase = (size_t)bb * IMG + base_px +
                           (size_t)(xr0 >> 1) * 128 + (xr0 & 1) * 4;
            int so_off = (xr0 >> 1) * 8 + (xr0 & 1) * 4;
            float4 o0 = *(const float4*)&sO[xc0 * SP_ST + so_off];
            float4 o1 = *(const float4*)&sO[xc1 * SP_ST + so_off];
            o0.x += xA.x; o0.y += xA.y; o0.z += xA.z; o0.w += xA.w;
            o1.x += xB.x; o1.y += xB.y; o1.z += xB.z; o1.w += xB.w;
            *(float4*)(outp + gbase + (size_t)(cc * 32 + xc0) * HW) = o0;
            *(float4*)(outp + gbase + (size_t)(cc * 32 + xc1) * HW) = o1;
            if (cc < 7) {
                xA = *(const float4*)(xlo + gbase + (size_t)((cc + 1) * 32 + xc0) * HW);
                xB = *(const float4*)(xlo + gbase + (size_t)((cc + 1) * 32 + xc1) * HW);
            }
        }
    }
}

// ---------------------------------------------------------------------------
// Launcher
// ---------------------------------------------------------------------------
extern "C" void kernel_launch(void* const* d_in, const int* in_sizes, int n_in,
                              void* d_out, int out_size)
{
    const float* x_low  = (const float*)d_in[0];
    const float* x_high = (const float*)d_in[1];
    const float* wq     = (const float*)d_in[2];
    const float* wk     = (const float*)d_in[3];
    const float* gq     = (const float*)d_in[4];
    const float* bq     = (const float*)d_in[5];
    const float* gk     = (const float*)d_in[6];
    const float* bk     = (const float*)d_in[7];
    float* outp = (float*)d_out;

    prep_afrag<<<256, 256>>>(wq, wk);

    proj_mma<<<dim3(2, 1024, 2), 256>>>(x_low, x_high);

    stats_finalize<<<512, 128>>>();

    cudaFuncSetAttribute(attn_mma,
                         cudaFuncAttributeMaxDynamicSharedMemorySize,
                         AT_SMEM_BYTES);
    attn_mma<<<2048, 256, AT_SMEM_BYTES>>>(x_low, outp, gq, bq, gk, bk);
}